// round 1
// baseline (speedup 1.0000x reference)
#include <cuda_runtime.h>

#define Bq 2
#define Tn 2048
#define Dn 768
#define Hn 12
#define HSn 64
#define BTn (Bq*Tn)
#define DFFn (4*Dn)

// ---------------- scratch (static device globals; no allocations) -----------
__device__ float g_h[(size_t)BTn*Dn];     // ln1(x) / ln2(x2)
__device__ float g_q[(size_t)BTn*Dn];
__device__ float g_k[(size_t)BTn*Dn];
__device__ float g_v[(size_t)BTn*Dn];
__device__ float g_att[(size_t)BTn*Dn];   // attention output (head-concat)
__device__ float g_ff[(size_t)BTn*DFFn];  // relu(h2 W1 + b1)

// ---------------- LayerNorm: one row (768) per block, 256 threads -----------
__global__ __launch_bounds__(256) void ln_kernel(
    const float* __restrict__ X, const float* __restrict__ g,
    const float* __restrict__ b, float* __restrict__ Y)
{
    const int row = blockIdx.x;
    const float* xr = X + (size_t)row * Dn;
    float* yr = Y + (size_t)row * Dn;
    const int tid = threadIdx.x;

    float v[3];
    float s = 0.f, s2 = 0.f;
#pragma unroll
    for (int i = 0; i < 3; i++) {
        float t = xr[tid + 256 * i];
        v[i] = t; s += t; s2 += t * t;
    }
#pragma unroll
    for (int o = 16; o > 0; o >>= 1) {
        s  += __shfl_down_sync(0xffffffffu, s,  o);
        s2 += __shfl_down_sync(0xffffffffu, s2, o);
    }
    __shared__ float rs[8], rs2[8];
    __shared__ float sh_mean, sh_inv;
    const int w = tid >> 5, ln = tid & 31;
    if (ln == 0) { rs[w] = s; rs2[w] = s2; }
    __syncthreads();
    if (tid == 0) {
        float a = 0.f, a2 = 0.f;
#pragma unroll
        for (int i = 0; i < 8; i++) { a += rs[i]; a2 += rs2[i]; }
        float m = a * (1.f / Dn);
        float var = a2 * (1.f / Dn) - m * m;
        sh_mean = m;
        sh_inv = rsqrtf(var + 1e-5f);
    }
    __syncthreads();
    const float m = sh_mean, inv = sh_inv;
#pragma unroll
    for (int i = 0; i < 3; i++) {
        int c = tid + 256 * i;
        yr[c] = (v[i] - m) * inv * g[c] + b[c];
    }
}

// ---------------- SGEMM: C = A[M,K] * B[K,N] (+bias)(+relu)(+resid) ---------
// 128x128 tile, BK=8, 256 threads, 8x8 per-thread register tile.
// Assumes M%128==0, N%128==0, K%8==0 (true for all shapes here).
template<bool RELU, bool RESID>
__global__ __launch_bounds__(256) void sgemm_k(
    const float* __restrict__ A, const float* __restrict__ B,
    const float* __restrict__ bias, const float* __restrict__ R,
    float* __restrict__ C, int M, int N, int K)
{
    __shared__ float As[8][128];
    __shared__ float Bs[8][128];
    const int tid  = threadIdx.x;
    const int tx   = tid & 15, ty = tid >> 4;
    const int row0 = blockIdx.y * 128, col0 = blockIdx.x * 128;
    const int arow = tid >> 1,  acol = (tid & 1) * 4;
    const int brow = tid >> 5,  bcol = (tid & 31) * 4;

    float acc[8][8];
#pragma unroll
    for (int i = 0; i < 8; i++)
#pragma unroll
        for (int j = 0; j < 8; j++) acc[i][j] = 0.f;

    const float* Aptr = A + (size_t)(row0 + arow) * K + acol;
    const float* Bptr = B + (size_t)brow * N + col0 + bcol;

    for (int k0 = 0; k0 < K; k0 += 8) {
        float4 av = *(const float4*)(Aptr + k0);
        As[acol + 0][arow] = av.x;
        As[acol + 1][arow] = av.y;
        As[acol + 2][arow] = av.z;
        As[acol + 3][arow] = av.w;
        float4 bv = *(const float4*)(Bptr + (size_t)k0 * N);
        *(float4*)&Bs[brow][bcol] = bv;
        __syncthreads();
#pragma unroll
        for (int k = 0; k < 8; k++) {
            float4 a0 = *(const float4*)&As[k][ty * 8];
            float4 a1 = *(const float4*)&As[k][ty * 8 + 4];
            float4 b0 = *(const float4*)&Bs[k][tx * 8];
            float4 b1 = *(const float4*)&Bs[k][tx * 8 + 4];
            float a[8] = {a0.x, a0.y, a0.z, a0.w, a1.x, a1.y, a1.z, a1.w};
            float bb[8] = {b0.x, b0.y, b0.z, b0.w, b1.x, b1.y, b1.z, b1.w};
#pragma unroll
            for (int i = 0; i < 8; i++)
#pragma unroll
                for (int j = 0; j < 8; j++)
                    acc[i][j] += a[i] * bb[j];
        }
        __syncthreads();
    }

#pragma unroll
    for (int i = 0; i < 8; i++) {
        const int r = row0 + ty * 8 + i;
#pragma unroll
        for (int j = 0; j < 8; j++) {
            const int c = col0 + tx * 8 + j;
            float v = acc[i][j];
            if (bias) v += bias[c];
            if (RELU) v = fmaxf(v, 0.f);
            if (RESID) v += R[(size_t)r * N + c];
            C[(size_t)r * N + c] = v;
        }
    }
}

// ---------------- Fused attention (flash-style online softmax) --------------
// Grid: (T/64, H, B). Block: 256 threads (16x16).
// Each block: 64 queries of one head. Key tiles of 32.
// Q/K/V layout: [B, T, D] with head offset h*64 (head-interleaved).
__global__ __launch_bounds__(256) void attn_kernel(
    const float* __restrict__ Q, const float* __restrict__ K,
    const float* __restrict__ V, const int* __restrict__ msk,
    float* __restrict__ O)
{
    __shared__ float Qs[64][65];
    __shared__ float Ks[32][65];
    __shared__ float Vs[32][65];
    __shared__ float Ps[64][33];
    __shared__ int   ms[32];

    const int qt = blockIdx.x, h = blockIdx.y, b = blockIdx.z;
    const int tid = threadIdx.x;
    const int tx = tid & 15, ty = tid >> 4;
    const size_t base = (size_t)b * Tn * Dn + (size_t)h * HSn;
    const int q0 = qt * 64;

    for (int e = tid; e < 64 * 64; e += 256) {
        int r = e >> 6, c = e & 63;
        Qs[r][c] = Q[base + (size_t)(q0 + r) * Dn + c];
    }
    float m_r[4], l_r[4], o[4][4];
#pragma unroll
    for (int i = 0; i < 4; i++) {
        m_r[i] = -1e30f; l_r[i] = 0.f;
#pragma unroll
        for (int j = 0; j < 4; j++) o[i][j] = 0.f;
    }
    __syncthreads();

    const float rs = 0.03608439182435161f;  // 768^-0.5 (NOTE: embed_dim, not hs)

    for (int kt = 0; kt < Tn; kt += 32) {
        for (int e = tid; e < 32 * 64; e += 256) {
            int r = e >> 6, c = e & 63;
            size_t gi = base + (size_t)(kt + r) * Dn + c;
            Ks[r][c] = K[gi];
            Vs[r][c] = V[gi];
        }
        if (tid < 32) ms[tid] = msk[b * Tn + kt + tid];
        __syncthreads();

        // S = Q K^T  (64x32, each thread 4x2)
        float s[4][2];
#pragma unroll
        for (int i = 0; i < 4; i++) { s[i][0] = 0.f; s[i][1] = 0.f; }
#pragma unroll 16
        for (int k = 0; k < 64; k++) {
            float k0v = Ks[tx * 2][k], k1v = Ks[tx * 2 + 1][k];
#pragma unroll
            for (int i = 0; i < 4; i++) {
                float qv = Qs[ty * 4 + i][k];
                s[i][0] += qv * k0v;
                s[i][1] += qv * k1v;
            }
        }
        const int mk0 = ms[tx * 2], mk1 = ms[tx * 2 + 1];
#pragma unroll
        for (int i = 0; i < 4; i++) {
            s[i][0] = mk0 ? s[i][0] * rs : -1e30f;
            s[i][1] = mk1 ? s[i][1] * rs : -1e30f;
            float mt = fmaxf(s[i][0], s[i][1]);
#pragma unroll
            for (int off = 8; off > 0; off >>= 1)
                mt = fmaxf(mt, __shfl_xor_sync(0xffffffffu, mt, off));
            float mn = fmaxf(m_r[i], mt);
            float alpha = __expf(m_r[i] - mn);
            float p0 = __expf(s[i][0] - mn);
            float p1 = __expf(s[i][1] - mn);
            Ps[ty * 4 + i][tx * 2]     = p0;
            Ps[ty * 4 + i][tx * 2 + 1] = p1;
            float rsum = p0 + p1;
#pragma unroll
            for (int off = 8; off > 0; off >>= 1)
                rsum += __shfl_xor_sync(0xffffffffu, rsum, off);
            l_r[i] = l_r[i] * alpha + rsum;
            m_r[i] = mn;
#pragma unroll
            for (int j = 0; j < 4; j++) o[i][j] *= alpha;
        }
        __syncthreads();

        // O += P V  (64x64 += 64x32 * 32x64, each thread 4x4)
#pragma unroll 8
        for (int k = 0; k < 32; k++) {
            float vv[4];
#pragma unroll
            for (int j = 0; j < 4; j++) vv[j] = Vs[k][tx * 4 + j];
#pragma unroll
            for (int i = 0; i < 4; i++) {
                float p = Ps[ty * 4 + i][k];
#pragma unroll
                for (int j = 0; j < 4; j++) o[i][j] += p * vv[j];
            }
        }
        __syncthreads();
    }

#pragma unroll
    for (int i = 0; i < 4; i++) {
        float invl = 1.f / l_r[i];
#pragma unroll
        for (int j = 0; j < 4; j++)
            O[base + (size_t)(q0 + ty * 4 + i) * Dn + tx * 4 + j] = o[i][j] * invl;
    }
}

// ---------------- launch ----------------------------------------------------
extern "C" void kernel_launch(void* const* d_in, const int* in_sizes, int n_in,
                              void* d_out, int out_size)
{
    (void)in_sizes; (void)n_in; (void)out_size;
    const float* x    = (const float*)d_in[0];
    const int*   mask = (const int*)d_in[1];
    const float* Wq   = (const float*)d_in[2];
    const float* Wk   = (const float*)d_in[3];
    const float* Wv   = (const float*)d_in[4];
    const float* Wo   = (const float*)d_in[5];
    const float* bo   = (const float*)d_in[6];
    const float* l1g  = (const float*)d_in[7];
    const float* l1b  = (const float*)d_in[8];
    const float* l2g  = (const float*)d_in[9];
    const float* l2b  = (const float*)d_in[10];
    const float* W1   = (const float*)d_in[11];
    const float* b1   = (const float*)d_in[12];
    const float* W2   = (const float*)d_in[13];
    const float* b2   = (const float*)d_in[14];
    float* out = (float*)d_out;

    float *ph, *pq, *pk, *pv, *pa, *pf;
    cudaGetSymbolAddress((void**)&ph, g_h);
    cudaGetSymbolAddress((void**)&pq, g_q);
    cudaGetSymbolAddress((void**)&pk, g_k);
    cudaGetSymbolAddress((void**)&pv, g_v);
    cudaGetSymbolAddress((void**)&pa, g_att);
    cudaGetSymbolAddress((void**)&pf, g_ff);

    // 1) h = ln1(x)
    ln_kernel<<<BTn, 256>>>(x, l1g, l1b, ph);

    // 2) Q, K, V = h @ {Wq, Wk, Wv}
    dim3 g768(Dn / 128, BTn / 128);
    sgemm_k<false, false><<<g768, 256>>>(ph, Wq, nullptr, nullptr, pq, BTn, Dn, Dn);
    sgemm_k<false, false><<<g768, 256>>>(ph, Wk, nullptr, nullptr, pk, BTn, Dn, Dn);
    sgemm_k<false, false><<<g768, 256>>>(ph, Wv, nullptr, nullptr, pv, BTn, Dn, Dn);

    // 3) fused attention (softmax(QK^T * d^-0.5 + mask) V), head-concat layout
    attn_kernel<<<dim3(Tn / 64, Hn, Bq), 256>>>(pq, pk, pv, mask, pa);

    // 4) x2 = x + att @ Wo + bo  -> d_out
    sgemm_k<false, true><<<g768, 256>>>(pa, Wo, bo, x, out, BTn, Dn, Dn);

    // 5) h2 = ln2(x2)
    ln_kernel<<<BTn, 256>>>(out, l2g, l2b, ph);

    // 6) ff = relu(h2 @ W1 + b1)
    sgemm_k<true, false><<<dim3(DFFn / 128, BTn / 128), 256>>>(
        ph, W1, b1, nullptr, pf, BTn, DFFn, Dn);

    // 7) out = x2 + ff @ W2 + b2
    sgemm_k<false, true><<<g768, 256>>>(pf, W2, b2, out, out, BTn, Dn, DFFn);
}

// round 3
// speedup vs baseline: 1.5899x; 1.5899x over previous
#include <cuda_runtime.h>
#include <cstdint>

#define Bq 2
#define Tn 2048
#define Dn 768
#define Hn 12
#define HSn 64
#define BTn (Bq*Tn)
#define DFFn (4*Dn)
#define QKVs 2304

// ---------------- scratch (static device globals; no allocations) -----------
__device__ float g_h[(size_t)BTn*Dn];       // ln1(x) / ln2(x2)
__device__ float g_qkv[(size_t)BTn*QKVs];   // [q|k|v] interleaved per row
__device__ float g_att[(size_t)BTn*Dn];     // attention output (head-concat)
__device__ float g_ff[(size_t)BTn*DFFn];    // relu(h2 W1 + b1)
// transposed weights: wqT,wkT,wvT (contiguous = [2304][768]), woT, w1T, w2T
__device__ float g_wt[4*589824 + 2*2359296];

// ---------------- helpers ----------------------------------------------------
__device__ __forceinline__ uint32_t f2tf(float f) {
    uint32_t r;
    asm("cvt.rna.tf32.f32 %0, %1;" : "=r"(r) : "f"(f));
    return r;
}
__device__ __forceinline__ void mma8(float* d, const uint32_t* a, const uint32_t* b) {
    asm volatile(
        "mma.sync.aligned.m16n8k8.row.col.f32.tf32.tf32.f32 "
        "{%0,%1,%2,%3}, {%4,%5,%6,%7}, {%8,%9}, {%0,%1,%2,%3};"
        : "+f"(d[0]), "+f"(d[1]), "+f"(d[2]), "+f"(d[3])
        : "r"(a[0]), "r"(a[1]), "r"(a[2]), "r"(a[3]), "r"(b[0]), "r"(b[1]));
}

// ============== tf32 mma.sync GEMM: C = A[M,K] * BT[N,K]^T ===================
// 128x128 CTA tile, BK=16, 256 threads (8 warps), warp tile 64x32.
// Smem [k][m]/[k][n] with stride 136 (pad 8) -> conflict-free fragment loads.
template<bool RELU, bool RESID>
__global__ __launch_bounds__(256) void mgemm_k(
    const float* __restrict__ A, const float* __restrict__ BT,
    const float* __restrict__ bias, const float* __restrict__ R,
    float* __restrict__ C, int M, int N, int K)
{
    __shared__ uint32_t As[16][136];
    __shared__ uint32_t Bs[16][136];

    const int tid = threadIdx.x;
    const int wid = tid >> 5, lane = tid & 31;
    const int g = lane >> 2, cc4 = lane & 3;
    const int wm = wid & 1, wn = wid >> 1;          // warps 2 (M) x 4 (N)
    const int m0 = blockIdx.y * 128, n0 = blockIdx.x * 128;

    // staging map: row = tid>>1 (0..127), kcol = (tid&1)*8, two float4 each
    const int srow = tid >> 1, scol = (tid & 1) * 8;
    const float* Ag = A  + (size_t)(m0 + srow) * K + scol;
    const float* Bg = BT + (size_t)(n0 + srow) * K + scol;

    float acc[4][4][4];
#pragma unroll
    for (int i = 0; i < 4; i++)
#pragma unroll
        for (int j = 0; j < 4; j++)
#pragma unroll
            for (int e = 0; e < 4; e++) acc[i][j][e] = 0.f;

    const int NC = K >> 4;
    float4 pa0, pa1, pb0, pb1;

    // preload tile 0
    pa0 = *(const float4*)(Ag);
    pa1 = *(const float4*)(Ag + 4);
    pb0 = *(const float4*)(Bg);
    pb1 = *(const float4*)(Bg + 4);
#define STS_TILE() do { \
    As[scol + 0][srow] = f2tf(pa0.x); As[scol + 1][srow] = f2tf(pa0.y); \
    As[scol + 2][srow] = f2tf(pa0.z); As[scol + 3][srow] = f2tf(pa0.w); \
    As[scol + 4][srow] = f2tf(pa1.x); As[scol + 5][srow] = f2tf(pa1.y); \
    As[scol + 6][srow] = f2tf(pa1.z); As[scol + 7][srow] = f2tf(pa1.w); \
    Bs[scol + 0][srow] = f2tf(pb0.x); Bs[scol + 1][srow] = f2tf(pb0.y); \
    Bs[scol + 2][srow] = f2tf(pb0.z); Bs[scol + 3][srow] = f2tf(pb0.w); \
    Bs[scol + 4][srow] = f2tf(pb1.x); Bs[scol + 5][srow] = f2tf(pb1.y); \
    Bs[scol + 6][srow] = f2tf(pb1.z); Bs[scol + 7][srow] = f2tf(pb1.w); \
    } while (0)
    STS_TILE();
    __syncthreads();

    for (int c = 0; c < NC; c++) {
        if (c + 1 < NC) {
            const float* Agn = Ag + (c + 1) * 16;
            const float* Bgn = Bg + (c + 1) * 16;
            pa0 = *(const float4*)(Agn);
            pa1 = *(const float4*)(Agn + 4);
            pb0 = *(const float4*)(Bgn);
            pb1 = *(const float4*)(Bgn + 4);
        }
#pragma unroll
        for (int s = 0; s < 2; s++) {
            uint32_t af[4][4], bf[4][2];
            const int kk = s * 8 + cc4;
#pragma unroll
            for (int i = 0; i < 4; i++) {
                const int mm = wm * 64 + i * 16 + g;
                af[i][0] = As[kk    ][mm];
                af[i][1] = As[kk    ][mm + 8];
                af[i][2] = As[kk + 4][mm];
                af[i][3] = As[kk + 4][mm + 8];
            }
#pragma unroll
            for (int j = 0; j < 4; j++) {
                const int nn = wn * 32 + j * 8 + g;
                bf[j][0] = Bs[kk    ][nn];
                bf[j][1] = Bs[kk + 4][nn];
            }
#pragma unroll
            for (int i = 0; i < 4; i++)
#pragma unroll
                for (int j = 0; j < 4; j++)
                    mma8(acc[i][j], af[i], bf[j]);
        }
        __syncthreads();
        if (c + 1 < NC) {
            STS_TILE();
            __syncthreads();
        }
    }
#undef STS_TILE

    // epilogue: thread owns rows (g, g+8) of each 16-row m-tile, cols 2*cc4(+1)
#pragma unroll
    for (int i = 0; i < 4; i++) {
        const int r0 = m0 + wm * 64 + i * 16 + g;
        const int r1 = r0 + 8;
#pragma unroll
        for (int j = 0; j < 4; j++) {
            const int col = n0 + wn * 32 + j * 8 + cc4 * 2;
            float v0 = acc[i][j][0], v1 = acc[i][j][1];
            float v2 = acc[i][j][2], v3 = acc[i][j][3];
            if (bias) {
                const float b0 = bias[col], b1 = bias[col + 1];
                v0 += b0; v1 += b1; v2 += b0; v3 += b1;
            }
            if (RELU) {
                v0 = fmaxf(v0, 0.f); v1 = fmaxf(v1, 0.f);
                v2 = fmaxf(v2, 0.f); v3 = fmaxf(v3, 0.f);
            }
            if (RESID) {
                const float2 ra = *(const float2*)&R[(size_t)r0 * N + col];
                const float2 rb = *(const float2*)&R[(size_t)r1 * N + col];
                v0 += ra.x; v1 += ra.y; v2 += rb.x; v3 += rb.y;
            }
            *(float2*)&C[(size_t)r0 * N + col] = make_float2(v0, v1);
            *(float2*)&C[(size_t)r1 * N + col] = make_float2(v2, v3);
        }
    }
}

// ---------------- transpose: out[N,K] = in[K,N]^T ----------------------------
__global__ __launch_bounds__(256) void transpose_k(
    const float* __restrict__ in, float* __restrict__ out, int Kd, int Nd)
{
    __shared__ float t[32][33];
    const int n0 = blockIdx.x * 32, k0 = blockIdx.y * 32;
    const int x = threadIdx.x, y = threadIdx.y;
#pragma unroll
    for (int dy = 0; dy < 32; dy += 8)
        t[y + dy][x] = in[(size_t)(k0 + y + dy) * Nd + n0 + x];
    __syncthreads();
#pragma unroll
    for (int dy = 0; dy < 32; dy += 8)
        out[(size_t)(n0 + y + dy) * Kd + k0 + x] = t[x][y + dy];
}

// ---------------- LayerNorm: one row (768) per block, 256 threads -----------
__global__ __launch_bounds__(256) void ln_kernel(
    const float* __restrict__ X, const float* __restrict__ g,
    const float* __restrict__ b, float* __restrict__ Y)
{
    const int row = blockIdx.x;
    const float* xr = X + (size_t)row * Dn;
    float* yr = Y + (size_t)row * Dn;
    const int tid = threadIdx.x;

    float v[3];
    float s = 0.f, s2 = 0.f;
#pragma unroll
    for (int i = 0; i < 3; i++) {
        float t = xr[tid + 256 * i];
        v[i] = t; s += t; s2 += t * t;
    }
#pragma unroll
    for (int o = 16; o > 0; o >>= 1) {
        s  += __shfl_down_sync(0xffffffffu, s,  o);
        s2 += __shfl_down_sync(0xffffffffu, s2, o);
    }
    __shared__ float rs[8], rs2[8];
    __shared__ float sh_mean, sh_inv;
    const int w = tid >> 5, ln = tid & 31;
    if (ln == 0) { rs[w] = s; rs2[w] = s2; }
    __syncthreads();
    if (tid == 0) {
        float a = 0.f, a2 = 0.f;
#pragma unroll
        for (int i = 0; i < 8; i++) { a += rs[i]; a2 += rs2[i]; }
        float m = a * (1.f / Dn);
        float var = a2 * (1.f / Dn) - m * m;
        sh_mean = m;
        sh_inv = rsqrtf(var + 1e-5f);
    }
    __syncthreads();
    const float m = sh_mean, inv = sh_inv;
#pragma unroll
    for (int i = 0; i < 3; i++) {
        int c = tid + 256 * i;
        yr[c] = (v[i] - m) * inv * g[c] + b[c];
    }
}

// ---------------- Fused attention (flash-style online softmax) --------------
// QKV packed: row stride QKVs; q at +0, k at +768, v at +1536.
__global__ __launch_bounds__(256) void attn_kernel(
    const float* __restrict__ QKV, const int* __restrict__ msk,
    float* __restrict__ O)
{
    __shared__ float Qs[64][65];
    __shared__ float Ks[32][65];
    __shared__ float Vs[32][65];
    __shared__ float Ps[64][33];
    __shared__ int   ms[32];

    const int qt = blockIdx.x, h = blockIdx.y, b = blockIdx.z;
    const int tid = threadIdx.x;
    const int tx = tid & 15, ty = tid >> 4;
    const size_t base = (size_t)b * Tn * QKVs + (size_t)h * HSn;
    const size_t obase = (size_t)b * Tn * Dn + (size_t)h * HSn;
    const int q0 = qt * 64;

    for (int e = tid; e < 64 * 64; e += 256) {
        int r = e >> 6, c = e & 63;
        Qs[r][c] = QKV[base + (size_t)(q0 + r) * QKVs + c];
    }
    float m_r[4], l_r[4], o[4][4];
#pragma unroll
    for (int i = 0; i < 4; i++) {
        m_r[i] = -1e30f; l_r[i] = 0.f;
#pragma unroll
        for (int j = 0; j < 4; j++) o[i][j] = 0.f;
    }
    __syncthreads();

    const float rs = 0.03608439182435161f;  // 768^-0.5 (embed_dim, not hs)

    for (int kt = 0; kt < Tn; kt += 32) {
        for (int e = tid; e < 32 * 64; e += 256) {
            int r = e >> 6, c = e & 63;
            size_t gi = base + (size_t)(kt + r) * QKVs + c;
            Ks[r][c] = QKV[gi + 768];
            Vs[r][c] = QKV[gi + 1536];
        }
        if (tid < 32) ms[tid] = msk[b * Tn + kt + tid];
        __syncthreads();

        float s[4][2];
#pragma unroll
        for (int i = 0; i < 4; i++) { s[i][0] = 0.f; s[i][1] = 0.f; }
#pragma unroll 16
        for (int k = 0; k < 64; k++) {
            float k0v = Ks[tx * 2][k], k1v = Ks[tx * 2 + 1][k];
#pragma unroll
            for (int i = 0; i < 4; i++) {
                float qv = Qs[ty * 4 + i][k];
                s[i][0] += qv * k0v;
                s[i][1] += qv * k1v;
            }
        }
        const int mk0 = ms[tx * 2], mk1 = ms[tx * 2 + 1];
#pragma unroll
        for (int i = 0; i < 4; i++) {
            s[i][0] = mk0 ? s[i][0] * rs : -1e30f;
            s[i][1] = mk1 ? s[i][1] * rs : -1e30f;
            float mt = fmaxf(s[i][0], s[i][1]);
#pragma unroll
            for (int off = 8; off > 0; off >>= 1)
                mt = fmaxf(mt, __shfl_xor_sync(0xffffffffu, mt, off));
            float mn = fmaxf(m_r[i], mt);
            float alpha = __expf(m_r[i] - mn);
            float p0 = __expf(s[i][0] - mn);
            float p1 = __expf(s[i][1] - mn);
            Ps[ty * 4 + i][tx * 2]     = p0;
            Ps[ty * 4 + i][tx * 2 + 1] = p1;
            float rsum = p0 + p1;
#pragma unroll
            for (int off = 8; off > 0; off >>= 1)
                rsum += __shfl_xor_sync(0xffffffffu, rsum, off);
            l_r[i] = l_r[i] * alpha + rsum;
            m_r[i] = mn;
#pragma unroll
            for (int j = 0; j < 4; j++) o[i][j] *= alpha;
        }
        __syncthreads();

#pragma unroll 8
        for (int k = 0; k < 32; k++) {
            float vv[4];
#pragma unroll
            for (int j = 0; j < 4; j++) vv[j] = Vs[k][tx * 4 + j];
#pragma unroll
            for (int i = 0; i < 4; i++) {
                float p = Ps[ty * 4 + i][k];
#pragma unroll
                for (int j = 0; j < 4; j++) o[i][j] += p * vv[j];
            }
        }
        __syncthreads();
    }

#pragma unroll
    for (int i = 0; i < 4; i++) {
        float invl = 1.f / l_r[i];
#pragma unroll
        for (int j = 0; j < 4; j++)
            O[obase + (size_t)(q0 + ty * 4 + i) * Dn + tx * 4 + j] = o[i][j] * invl;
    }
}

// ---------------- launch ----------------------------------------------------
extern "C" void kernel_launch(void* const* d_in, const int* in_sizes, int n_in,
                              void* d_out, int out_size)
{
    (void)in_sizes; (void)n_in; (void)out_size;
    const float* x    = (const float*)d_in[0];
    const int*   mask = (const int*)d_in[1];
    const float* Wq   = (const float*)d_in[2];
    const float* Wk   = (const float*)d_in[3];
    const float* Wv   = (const float*)d_in[4];
    const float* Wo   = (const float*)d_in[5];
    const float* bo   = (const float*)d_in[6];
    const float* l1g  = (const float*)d_in[7];
    const float* l1b  = (const float*)d_in[8];
    const float* l2g  = (const float*)d_in[9];
    const float* l2b  = (const float*)d_in[10];
    const float* W1   = (const float*)d_in[11];
    const float* b1   = (const float*)d_in[12];
    const float* W2   = (const float*)d_in[13];
    const float* b2   = (const float*)d_in[14];
    float* out = (float*)d_out;

    float *ph, *pqkv, *pa, *pf, *pw;
    cudaGetSymbolAddress((void**)&ph, g_h);
    cudaGetSymbolAddress((void**)&pqkv, g_qkv);
    cudaGetSymbolAddress((void**)&pa, g_att);
    cudaGetSymbolAddress((void**)&pf, g_ff);
    cudaGetSymbolAddress((void**)&pw, g_wt);

    float* wqkvT = pw;                       // [2304][768] (wq|wk|wv stacked)
    float* woT   = pw + 3 * 589824;
    float* w1T   = pw + 4 * 589824;
    float* w2T   = pw + 4 * 589824 + 2359296;

    // 0) transpose weights to [N,K] K-major
    dim3 tb(32, 8);
    transpose_k<<<dim3(Dn / 32, Dn / 32), tb>>>(Wq, wqkvT, Dn, Dn);
    transpose_k<<<dim3(Dn / 32, Dn / 32), tb>>>(Wk, wqkvT + 589824, Dn, Dn);
    transpose_k<<<dim3(Dn / 32, Dn / 32), tb>>>(Wv, wqkvT + 2 * 589824, Dn, Dn);
    transpose_k<<<dim3(Dn / 32, Dn / 32), tb>>>(Wo, woT, Dn, Dn);
    transpose_k<<<dim3(DFFn / 32, Dn / 32), tb>>>(W1, w1T, Dn, DFFn);
    transpose_k<<<dim3(Dn / 32, DFFn / 32), tb>>>(W2, w2T, DFFn, Dn);

    // 1) h = ln1(x)
    ln_kernel<<<BTn, 256>>>(x, l1g, l1b, ph);

    // 2) qkv = h @ [Wq|Wk|Wv]  (one fused tf32 mma GEMM, N=2304)
    mgemm_k<false, false><<<dim3(QKVs / 128, BTn / 128), 256>>>(
        ph, wqkvT, nullptr, nullptr, pqkv, BTn, QKVs, Dn);

    // 3) fused attention
    attn_kernel<<<dim3(Tn / 64, Hn, Bq), 256>>>(pqkv, mask, pa);

    // 4) x2 = x + att @ Wo + bo  -> d_out
    mgemm_k<false, true><<<dim3(Dn / 128, BTn / 128), 256>>>(
        pa, woT, bo, x, out, BTn, Dn, Dn);

    // 5) h2 = ln2(x2)
    ln_kernel<<<BTn, 256>>>(out, l2g, l2b, ph);

    // 6) ff = relu(h2 @ W1 + b1)
    mgemm_k<true, false><<<dim3(DFFn / 128, BTn / 128), 256>>>(
        ph, w1T, b1, nullptr, pf, BTn, DFFn, Dn);

    // 7) out = x2 + ff @ W2 + b2
    mgemm_k<false, true><<<dim3(Dn / 128, BTn / 128), 256>>>(
        pf, w2T, b2, out, out, BTn, Dn, DFFn);
}

// round 4
// speedup vs baseline: 2.6483x; 1.6657x over previous
#include <cuda_runtime.h>
#include <cstdint>

#define Bq 2
#define Tn 2048
#define Dn 768
#define Hn 12
#define HSn 64
#define BTn (Bq*Tn)
#define DFFn (4*Dn)
#define QKVs 2304

// ---------------- scratch (static device globals; no allocations) -----------
__device__ float g_h[(size_t)BTn*Dn];       // ln1(x) / ln2(x2)
__device__ float g_qkv[(size_t)BTn*QKVs];   // [q|k|v] interleaved per row
__device__ float g_att[(size_t)BTn*Dn];     // attention output (head-concat)
__device__ float g_ff[(size_t)BTn*DFFn];    // relu(h2 W1 + b1)
__device__ float g_wt[4*589824 + 2*2359296];

// ---------------- helpers ----------------------------------------------------
__device__ __forceinline__ uint32_t f2tf(float f) {
    uint32_t r;
    asm("cvt.rna.tf32.f32 %0, %1;" : "=r"(r) : "f"(f));
    return r;
}
__device__ __forceinline__ void mma8(float* d, const uint32_t* a, const uint32_t* b) {
    asm volatile(
        "mma.sync.aligned.m16n8k8.row.col.f32.tf32.tf32.f32 "
        "{%0,%1,%2,%3}, {%4,%5,%6,%7}, {%8,%9}, {%0,%1,%2,%3};"
        : "+f"(d[0]), "+f"(d[1]), "+f"(d[2]), "+f"(d[3])
        : "r"(a[0]), "r"(a[1]), "r"(a[2]), "r"(a[3]), "r"(b[0]), "r"(b[1]));
}

// ============== tf32 mma.sync GEMM: C = A[M,K] * BT[N,K]^T ===================
template<bool RELU, bool RESID>
__global__ __launch_bounds__(256) void mgemm_k(
    const float* __restrict__ A, const float* __restrict__ BT,
    const float* __restrict__ bias, const float* __restrict__ R,
    float* __restrict__ C, int M, int N, int K)
{
    __shared__ uint32_t As[16][136];
    __shared__ uint32_t Bs[16][136];

    const int tid = threadIdx.x;
    const int wid = tid >> 5, lane = tid & 31;
    const int g = lane >> 2, cc4 = lane & 3;
    const int wm = wid & 1, wn = wid >> 1;
    const int m0 = blockIdx.y * 128, n0 = blockIdx.x * 128;

    const int srow = tid >> 1, scol = (tid & 1) * 8;
    const float* Ag = A  + (size_t)(m0 + srow) * K + scol;
    const float* Bg = BT + (size_t)(n0 + srow) * K + scol;

    float acc[4][4][4];
#pragma unroll
    for (int i = 0; i < 4; i++)
#pragma unroll
        for (int j = 0; j < 4; j++)
#pragma unroll
            for (int e = 0; e < 4; e++) acc[i][j][e] = 0.f;

    const int NC = K >> 4;
    float4 pa0, pa1, pb0, pb1;

    pa0 = *(const float4*)(Ag);
    pa1 = *(const float4*)(Ag + 4);
    pb0 = *(const float4*)(Bg);
    pb1 = *(const float4*)(Bg + 4);
#define STS_TILE() do { \
    As[scol + 0][srow] = f2tf(pa0.x); As[scol + 1][srow] = f2tf(pa0.y); \
    As[scol + 2][srow] = f2tf(pa0.z); As[scol + 3][srow] = f2tf(pa0.w); \
    As[scol + 4][srow] = f2tf(pa1.x); As[scol + 5][srow] = f2tf(pa1.y); \
    As[scol + 6][srow] = f2tf(pa1.z); As[scol + 7][srow] = f2tf(pa1.w); \
    Bs[scol + 0][srow] = f2tf(pb0.x); Bs[scol + 1][srow] = f2tf(pb0.y); \
    Bs[scol + 2][srow] = f2tf(pb0.z); Bs[scol + 3][srow] = f2tf(pb0.w); \
    Bs[scol + 4][srow] = f2tf(pb1.x); Bs[scol + 5][srow] = f2tf(pb1.y); \
    Bs[scol + 6][srow] = f2tf(pb1.z); Bs[scol + 7][srow] = f2tf(pb1.w); \
    } while (0)
    STS_TILE();
    __syncthreads();

    for (int c = 0; c < NC; c++) {
        if (c + 1 < NC) {
            const float* Agn = Ag + (c + 1) * 16;
            const float* Bgn = Bg + (c + 1) * 16;
            pa0 = *(const float4*)(Agn);
            pa1 = *(const float4*)(Agn + 4);
            pb0 = *(const float4*)(Bgn);
            pb1 = *(const float4*)(Bgn + 4);
        }
#pragma unroll
        for (int s = 0; s < 2; s++) {
            uint32_t af[4][4], bf[4][2];
            const int kk = s * 8 + cc4;
#pragma unroll
            for (int i = 0; i < 4; i++) {
                const int mm = wm * 64 + i * 16 + g;
                af[i][0] = As[kk    ][mm];
                af[i][1] = As[kk    ][mm + 8];
                af[i][2] = As[kk + 4][mm];
                af[i][3] = As[kk + 4][mm + 8];
            }
#pragma unroll
            for (int j = 0; j < 4; j++) {
                const int nn = wn * 32 + j * 8 + g;
                bf[j][0] = Bs[kk    ][nn];
                bf[j][1] = Bs[kk + 4][nn];
            }
#pragma unroll
            for (int i = 0; i < 4; i++)
#pragma unroll
                for (int j = 0; j < 4; j++)
                    mma8(acc[i][j], af[i], bf[j]);
        }
        __syncthreads();
        if (c + 1 < NC) {
            STS_TILE();
            __syncthreads();
        }
    }
#undef STS_TILE

#pragma unroll
    for (int i = 0; i < 4; i++) {
        const int r0 = m0 + wm * 64 + i * 16 + g;
        const int r1 = r0 + 8;
#pragma unroll
        for (int j = 0; j < 4; j++) {
            const int col = n0 + wn * 32 + j * 8 + cc4 * 2;
            float v0 = acc[i][j][0], v1 = acc[i][j][1];
            float v2 = acc[i][j][2], v3 = acc[i][j][3];
            if (bias) {
                const float b0 = bias[col], b1 = bias[col + 1];
                v0 += b0; v1 += b1; v2 += b0; v3 += b1;
            }
            if (RELU) {
                v0 = fmaxf(v0, 0.f); v1 = fmaxf(v1, 0.f);
                v2 = fmaxf(v2, 0.f); v3 = fmaxf(v3, 0.f);
            }
            if (RESID) {
                const float2 ra = *(const float2*)&R[(size_t)r0 * N + col];
                const float2 rb = *(const float2*)&R[(size_t)r1 * N + col];
                v0 += ra.x; v1 += ra.y; v2 += rb.x; v3 += rb.y;
            }
            *(float2*)&C[(size_t)r0 * N + col] = make_float2(v0, v1);
            *(float2*)&C[(size_t)r1 * N + col] = make_float2(v2, v3);
        }
    }
}

// ---------------- transpose: out[N,K] = in[K,N]^T ----------------------------
__global__ __launch_bounds__(256) void transpose_k(
    const float* __restrict__ in, float* __restrict__ out, int Kd, int Nd)
{
    __shared__ float t[32][33];
    const int n0 = blockIdx.x * 32, k0 = blockIdx.y * 32;
    const int x = threadIdx.x, y = threadIdx.y;
#pragma unroll
    for (int dy = 0; dy < 32; dy += 8)
        t[y + dy][x] = in[(size_t)(k0 + y + dy) * Nd + n0 + x];
    __syncthreads();
#pragma unroll
    for (int dy = 0; dy < 32; dy += 8)
        out[(size_t)(n0 + y + dy) * Kd + k0 + x] = t[x][y + dy];
}

// ---------------- LayerNorm ---------------------------------------------------
__global__ __launch_bounds__(256) void ln_kernel(
    const float* __restrict__ X, const float* __restrict__ g,
    const float* __restrict__ b, float* __restrict__ Y)
{
    const int row = blockIdx.x;
    const float* xr = X + (size_t)row * Dn;
    float* yr = Y + (size_t)row * Dn;
    const int tid = threadIdx.x;

    float v[3];
    float s = 0.f, s2 = 0.f;
#pragma unroll
    for (int i = 0; i < 3; i++) {
        float t = xr[tid + 256 * i];
        v[i] = t; s += t; s2 += t * t;
    }
#pragma unroll
    for (int o = 16; o > 0; o >>= 1) {
        s  += __shfl_down_sync(0xffffffffu, s,  o);
        s2 += __shfl_down_sync(0xffffffffu, s2, o);
    }
    __shared__ float rs[8], rs2[8];
    __shared__ float sh_mean, sh_inv;
    const int w = tid >> 5, ln = tid & 31;
    if (ln == 0) { rs[w] = s; rs2[w] = s2; }
    __syncthreads();
    if (tid == 0) {
        float a = 0.f, a2 = 0.f;
#pragma unroll
        for (int i = 0; i < 8; i++) { a += rs[i]; a2 += rs2[i]; }
        float m = a * (1.f / Dn);
        float var = a2 * (1.f / Dn) - m * m;
        sh_mean = m;
        sh_inv = rsqrtf(var + 1e-5f);
    }
    __syncthreads();
    const float m = sh_mean, inv = sh_inv;
#pragma unroll
    for (int i = 0; i < 3; i++) {
        int c = tid + 256 * i;
        yr[c] = (v[i] - m) * inv * g[c] + b[c];
    }
}

// ============ Tensor-core flash attention (tf32 mma, online softmax) ========
// Block: 128 queries of one (b,h); 8 warps, warp w owns rows w*16..w*16+15.
// Key tiles of 64. Q A-fragments live in registers across all key tiles.
// smem: Ps[128][68] (Q staging, then P), Ks[64][68], Vs[64][72], ms[64].
#define APAD 68
#define VPAD 72
#define ATT_SMEM ((128*APAD + 64*APAD + 64*VPAD) * 4 + 64 * 4)

__global__ void __launch_bounds__(256, 2) attn_mma_kernel(
    const float* __restrict__ QKV, const int* __restrict__ msk,
    float* __restrict__ O)
{
    extern __shared__ __align__(16) float sm[];
    float* Ps = sm;                       // [128][APAD]
    float* Ks = sm + 128 * APAD;          // [64][APAD]
    float* Vs = Ks + 64 * APAD;           // [64][VPAD]
    int*   ms = (int*)(Vs + 64 * VPAD);   // [64]
    uint32_t* Pu = (uint32_t*)Ps;
    uint32_t* Ku = (uint32_t*)Ks;
    uint32_t* Vu = (uint32_t*)Vs;

    const int qt = blockIdx.x, h = blockIdx.y, b = blockIdx.z;
    const int tid = threadIdx.x;
    const int w = tid >> 5, lane = tid & 31;
    const int g = lane >> 2, c4 = lane & 3;
    const size_t base  = (size_t)b * Tn * QKVs + (size_t)h * HSn;
    const size_t obase = (size_t)b * Tn * Dn + (size_t)h * HSn;
    const int q0 = qt * 128;

    // ---- stage Q (tf32) into Ps
#pragma unroll
    for (int e = 0; e < 8; e++) {
        int idx = tid + e * 256;
        int r = idx >> 4, cc = (idx & 15) * 4;
        float4 v = *(const float4*)&QKV[base + (size_t)(q0 + r) * QKVs + cc];
        *(uint4*)&Pu[r * APAD + cc] =
            make_uint4(f2tf(v.x), f2tf(v.y), f2tf(v.z), f2tf(v.w));
    }
    __syncthreads();

    // ---- Q fragments -> registers (A of m16n8k8)
    uint32_t qf[8][4];
#pragma unroll
    for (int kc = 0; kc < 8; kc++) {
        int r0 = (w * 16 + g) * APAD + kc * 8 + c4;
        qf[kc][0] = Pu[r0];
        qf[kc][1] = Pu[r0 + 8 * APAD];
        qf[kc][2] = Pu[r0 + 4];
        qf[kc][3] = Pu[r0 + 8 * APAD + 4];
    }
    __syncthreads();  // Ps now free for P

    float m0r = -1e30f, m1r = -1e30f, l0 = 0.f, l1 = 0.f;
    float o[8][4];
#pragma unroll
    for (int nt = 0; nt < 8; nt++)
#pragma unroll
        for (int e = 0; e < 4; e++) o[nt][e] = 0.f;

    const float rsc = 0.03608439182435161f;  // 768^-0.5 (embed_dim, not hs)

    for (int kt = 0; kt < Tn; kt += 64) {
        // ---- stage K, V (tf32)
#pragma unroll
        for (int e = 0; e < 4; e++) {
            int idx = tid + e * 256;
            int r = idx >> 4, cc = (idx & 15) * 4;
            size_t gi = base + (size_t)(kt + r) * QKVs + cc;
            float4 kv = *(const float4*)&QKV[gi + 768];
            float4 vv = *(const float4*)&QKV[gi + 1536];
            *(uint4*)&Ku[r * APAD + cc] =
                make_uint4(f2tf(kv.x), f2tf(kv.y), f2tf(kv.z), f2tf(kv.w));
            *(uint4*)&Vu[r * VPAD + cc] =
                make_uint4(f2tf(vv.x), f2tf(vv.y), f2tf(vv.z), f2tf(vv.w));
        }
        if (tid < 64) ms[tid] = msk[b * Tn + kt + tid];
        __syncthreads();

        // ---- S = Q K^T (64 MMAs)
        float s[8][4];
#pragma unroll
        for (int nt = 0; nt < 8; nt++)
#pragma unroll
            for (int e = 0; e < 4; e++) s[nt][e] = 0.f;
#pragma unroll
        for (int kc = 0; kc < 8; kc++) {
#pragma unroll
            for (int nt = 0; nt < 8; nt++) {
                uint32_t bf[2];
                int ka = (nt * 8 + g) * APAD + kc * 8 + c4;
                bf[0] = Ku[ka];
                bf[1] = Ku[ka + 4];
                mma8(s[nt], qf[kc], bf);
            }
        }

        // ---- mask + scale + online softmax on accumulator layout
        float mx0 = -1e30f, mx1 = -1e30f;
#pragma unroll
        for (int nt = 0; nt < 8; nt++) {
            const int mk0 = ms[nt * 8 + 2 * c4], mk1 = ms[nt * 8 + 2 * c4 + 1];
            s[nt][0] = mk0 ? s[nt][0] * rsc : -1e30f;
            s[nt][1] = mk1 ? s[nt][1] * rsc : -1e30f;
            s[nt][2] = mk0 ? s[nt][2] * rsc : -1e30f;
            s[nt][3] = mk1 ? s[nt][3] * rsc : -1e30f;
            mx0 = fmaxf(mx0, fmaxf(s[nt][0], s[nt][1]));
            mx1 = fmaxf(mx1, fmaxf(s[nt][2], s[nt][3]));
        }
        mx0 = fmaxf(mx0, __shfl_xor_sync(0xffffffffu, mx0, 1));
        mx0 = fmaxf(mx0, __shfl_xor_sync(0xffffffffu, mx0, 2));
        mx1 = fmaxf(mx1, __shfl_xor_sync(0xffffffffu, mx1, 1));
        mx1 = fmaxf(mx1, __shfl_xor_sync(0xffffffffu, mx1, 2));

        const float mn0 = fmaxf(m0r, mx0), mn1 = fmaxf(m1r, mx1);
        const float a0 = __expf(m0r - mn0), a1 = __expf(m1r - mn1);
        float rs0 = 0.f, rs1 = 0.f;
#pragma unroll
        for (int nt = 0; nt < 8; nt++) {
            float p0 = __expf(s[nt][0] - mn0);
            float p1 = __expf(s[nt][1] - mn0);
            float p2 = __expf(s[nt][2] - mn1);
            float p3 = __expf(s[nt][3] - mn1);
            rs0 += p0 + p1;
            rs1 += p2 + p3;
            int pa = (w * 16 + g) * APAD + nt * 8 + 2 * c4;
            Pu[pa]               = f2tf(p0);
            Pu[pa + 1]           = f2tf(p1);
            Pu[pa + 8 * APAD]     = f2tf(p2);
            Pu[pa + 8 * APAD + 1] = f2tf(p3);
        }
        rs0 += __shfl_xor_sync(0xffffffffu, rs0, 1);
        rs0 += __shfl_xor_sync(0xffffffffu, rs0, 2);
        rs1 += __shfl_xor_sync(0xffffffffu, rs1, 1);
        rs1 += __shfl_xor_sync(0xffffffffu, rs1, 2);
        l0 = l0 * a0 + rs0;
        l1 = l1 * a1 + rs1;
        m0r = mn0; m1r = mn1;
#pragma unroll
        for (int nt = 0; nt < 8; nt++) {
            o[nt][0] *= a0; o[nt][1] *= a0;
            o[nt][2] *= a1; o[nt][3] *= a1;
        }
        __syncwarp();

        // ---- O += P V (64 MMAs)
#pragma unroll
        for (int kc = 0; kc < 8; kc++) {
            uint32_t pf[4];
            int pa = (w * 16 + g) * APAD + kc * 8 + c4;
            pf[0] = Pu[pa];
            pf[1] = Pu[pa + 8 * APAD];
            pf[2] = Pu[pa + 4];
            pf[3] = Pu[pa + 8 * APAD + 4];
#pragma unroll
            for (int nt = 0; nt < 8; nt++) {
                uint32_t bf[2];
                int va = (kc * 8 + c4) * VPAD + nt * 8 + g;
                bf[0] = Vu[va];
                bf[1] = Vu[va + 4 * VPAD];
                mma8(o[nt], pf, bf);
            }
        }
        __syncthreads();
    }

    // ---- epilogue
    const float il0 = 1.f / l0, il1 = 1.f / l1;
    const int r0 = q0 + w * 16 + g;
#pragma unroll
    for (int nt = 0; nt < 8; nt++) {
        const int col = nt * 8 + 2 * c4;
        *(float2*)&O[obase + (size_t)r0 * Dn + col] =
            make_float2(o[nt][0] * il0, o[nt][1] * il0);
        *(float2*)&O[obase + (size_t)(r0 + 8) * Dn + col] =
            make_float2(o[nt][2] * il1, o[nt][3] * il1);
    }
}

// ---------------- launch ----------------------------------------------------
extern "C" void kernel_launch(void* const* d_in, const int* in_sizes, int n_in,
                              void* d_out, int out_size)
{
    (void)in_sizes; (void)n_in; (void)out_size;
    const float* x    = (const float*)d_in[0];
    const int*   mask = (const int*)d_in[1];
    const float* Wq   = (const float*)d_in[2];
    const float* Wk   = (const float*)d_in[3];
    const float* Wv   = (const float*)d_in[4];
    const float* Wo   = (const float*)d_in[5];
    const float* bo   = (const float*)d_in[6];
    const float* l1g  = (const float*)d_in[7];
    const float* l1b  = (const float*)d_in[8];
    const float* l2g  = (const float*)d_in[9];
    const float* l2b  = (const float*)d_in[10];
    const float* W1   = (const float*)d_in[11];
    const float* b1   = (const float*)d_in[12];
    const float* W2   = (const float*)d_in[13];
    const float* b2   = (const float*)d_in[14];
    float* out = (float*)d_out;

    float *ph, *pqkv, *pa, *pf, *pw;
    cudaGetSymbolAddress((void**)&ph, g_h);
    cudaGetSymbolAddress((void**)&pqkv, g_qkv);
    cudaGetSymbolAddress((void**)&pa, g_att);
    cudaGetSymbolAddress((void**)&pf, g_ff);
    cudaGetSymbolAddress((void**)&pw, g_wt);

    float* wqkvT = pw;                       // [2304][768] (wq|wk|wv stacked)
    float* woT   = pw + 3 * 589824;
    float* w1T   = pw + 4 * 589824;
    float* w2T   = pw + 4 * 589824 + 2359296;

    cudaFuncSetAttribute(attn_mma_kernel,
                         cudaFuncAttributeMaxDynamicSharedMemorySize, ATT_SMEM);

    // 0) transpose weights to [N,K] K-major
    dim3 tb(32, 8);
    transpose_k<<<dim3(Dn / 32, Dn / 32), tb>>>(Wq, wqkvT, Dn, Dn);
    transpose_k<<<dim3(Dn / 32, Dn / 32), tb>>>(Wk, wqkvT + 589824, Dn, Dn);
    transpose_k<<<dim3(Dn / 32, Dn / 32), tb>>>(Wv, wqkvT + 2 * 589824, Dn, Dn);
    transpose_k<<<dim3(Dn / 32, Dn / 32), tb>>>(Wo, woT, Dn, Dn);
    transpose_k<<<dim3(DFFn / 32, Dn / 32), tb>>>(W1, w1T, Dn, DFFn);
    transpose_k<<<dim3(Dn / 32, DFFn / 32), tb>>>(W2, w2T, DFFn, Dn);

    // 1) h = ln1(x)
    ln_kernel<<<BTn, 256>>>(x, l1g, l1b, ph);

    // 2) qkv = h @ [Wq|Wk|Wv]
    mgemm_k<false, false><<<dim3(QKVs / 128, BTn / 128), 256>>>(
        ph, wqkvT, nullptr, nullptr, pqkv, BTn, QKVs, Dn);

    // 3) tensor-core flash attention
    attn_mma_kernel<<<dim3(Tn / 128, Hn, Bq), 256, ATT_SMEM>>>(pqkv, mask, pa);

    // 4) x2 = x + att @ Wo + bo  -> d_out
    mgemm_k<false, true><<<dim3(Dn / 128, BTn / 128), 256>>>(
        pa, woT, bo, x, out, BTn, Dn, Dn);

    // 5) h2 = ln2(x2)
    ln_kernel<<<BTn, 256>>>(out, l2g, l2b, ph);

    // 6) ff = relu(h2 @ W1 + b1)
    mgemm_k<true, false><<<dim3(DFFn / 128, BTn / 128), 256>>>(
        ph, w1T, b1, nullptr, pf, BTn, DFFn, Dn);

    // 7) out = x2 + ff @ W2 + b2
    mgemm_k<false, true><<<dim3(Dn / 128, BTn / 128), 256>>>(
        pf, w2T, b2, out, out, BTn, Dn, DFFn);
}

// round 5
// speedup vs baseline: 3.7424x; 1.4131x over previous
#include <cuda_runtime.h>
#include <cstdint>

#define Bq 2
#define Tn 2048
#define Dn 768
#define Hn 12
#define HSn 64
#define BTn (Bq*Tn)
#define DFFn (4*Dn)
#define QKVs 2304

// ---------------- scratch (static device globals; no allocations) -----------
__device__ float g_h[(size_t)BTn*Dn];       // ln1(x) / ln2(x2)
__device__ float g_qkv[(size_t)BTn*QKVs];   // [q|k|v] interleaved per row
__device__ float g_att[(size_t)BTn*Dn];     // attention output (head-concat)
__device__ float g_ff[(size_t)BTn*DFFn];    // relu(h2 W1 + b1)
__device__ float g_wt[4*589824 + 2*2359296];

// ---------------- helpers ----------------------------------------------------
__device__ __forceinline__ uint32_t smem_to_u32(const void* p) {
    uint32_t a;
    asm("{ .reg .u64 t; cvta.to.shared.u64 t, %1; cvt.u32.u64 %0, t; }"
        : "=r"(a) : "l"(p));
    return a;
}
__device__ __forceinline__ void cp16(uint32_t s, const float* g) {
    asm volatile("cp.async.cg.shared.global [%0], [%1], 16;" :: "r"(s), "l"(g));
}
#define CP_COMMIT() asm volatile("cp.async.commit_group;" ::: "memory")
#define CP_WAIT(n)  asm volatile("cp.async.wait_group %0;" :: "n"(n) : "memory")

// raw f32 bits into tf32 mma: HW truncates mantissa (cutlass fast path)
__device__ __forceinline__ void mma8(float* d, const uint32_t* a, const uint32_t* b) {
    asm volatile(
        "mma.sync.aligned.m16n8k8.row.col.f32.tf32.tf32.f32 "
        "{%0,%1,%2,%3}, {%4,%5,%6,%7}, {%8,%9}, {%0,%1,%2,%3};"
        : "+f"(d[0]), "+f"(d[1]), "+f"(d[2]), "+f"(d[3])
        : "r"(a[0]), "r"(a[1]), "r"(a[2]), "r"(a[3]), "r"(b[0]), "r"(b[1]));
}

// ============== tf32 mma GEMM: C = A[M,K] * BT[N,K]^T ========================
// 128x128 CTA tile, BK=32, 256 threads (8 warps, 2x4), warp tile 64x32.
// cp.async double-buffered; smem row-major [m][36]/[n][36] (pad 4) -> 4g+c4
// bank mapping, conflict-free. Raw f32 bits (no cvt).
#define GSTRIDE 36
#define GSTAGE  (128*GSTRIDE)         // u32 per matrix per stage (4608)
#define GEMM_SMEM (2*2*GSTAGE*4)      // 73728 bytes

template<bool RELU, bool RESID>
__global__ __launch_bounds__(256) void mgemm_k(
    const float* __restrict__ A, const float* __restrict__ BT,
    const float* __restrict__ bias, const float* __restrict__ R,
    float* __restrict__ C, int M, int N, int K)
{
    extern __shared__ __align__(16) uint32_t smu[];
    const uint32_t sb = smem_to_u32(smu);

    const int tid = threadIdx.x;
    const int wid = tid >> 5, lane = tid & 31;
    const int g = lane >> 2, c4 = lane & 3;
    const int wm = wid & 1, wn = wid >> 1;
    const int m0 = blockIdx.y * 128, n0 = blockIdx.x * 128;

    // staging: thread covers rows rb, rb+32, rb+64, rb+96 at k-col cl..cl+3
    const int rb = tid >> 3, cl = (tid & 7) * 4;
    const float* Abase = A  + (size_t)(m0 + rb) * K + cl;
    const float* Bbase = BT + (size_t)(n0 + rb) * K + cl;

    float acc[4][4][4];
#pragma unroll
    for (int i = 0; i < 4; i++)
#pragma unroll
        for (int j = 0; j < 4; j++)
#pragma unroll
            for (int e = 0; e < 4; e++) acc[i][j][e] = 0.f;

    const int NC = K >> 5;

#define LOAD_STAGE(c_, s_) do { \
    const uint32_t _da = sb + (uint32_t)((s_) * 2 * GSTAGE) * 4u; \
    const uint32_t _db = _da + GSTAGE * 4u; \
    const int _ko = (c_) * 32; \
    _Pragma("unroll") \
    for (int _e = 0; _e < 4; _e++) { \
        const uint32_t _so = (uint32_t)(((_e * 32 + rb) * GSTRIDE + cl) * 4); \
        const size_t _go = (size_t)(_e * 32) * K + _ko; \
        cp16(_da + _so, Abase + _go); \
        cp16(_db + _so, Bbase + _go); \
    } } while (0)

    LOAD_STAGE(0, 0); CP_COMMIT();
    if (NC > 1) { LOAD_STAGE(1, 1); CP_COMMIT(); }

    for (int c = 0; c < NC; c++) {
        if (c + 1 < NC) { CP_WAIT(1); } else { CP_WAIT(0); }
        __syncthreads();

        const uint32_t* Asp = smu + (c & 1) * 2 * GSTAGE;
        const uint32_t* Bsp = Asp + GSTAGE;

#pragma unroll
        for (int s = 0; s < 4; s++) {
            const int kk = s * 8 + c4;
            uint32_t af[4][4], bf[4][2];
#pragma unroll
            for (int i = 0; i < 4; i++) {
                const int mm = (wm * 64 + i * 16 + g) * GSTRIDE;
                af[i][0] = Asp[mm + kk];
                af[i][1] = Asp[mm + 8 * GSTRIDE + kk];
                af[i][2] = Asp[mm + kk + 4];
                af[i][3] = Asp[mm + 8 * GSTRIDE + kk + 4];
            }
#pragma unroll
            for (int j = 0; j < 4; j++) {
                const int nn = (wn * 32 + j * 8 + g) * GSTRIDE;
                bf[j][0] = Bsp[nn + kk];
                bf[j][1] = Bsp[nn + kk + 4];
            }
#pragma unroll
            for (int i = 0; i < 4; i++)
#pragma unroll
                for (int j = 0; j < 4; j++)
                    mma8(acc[i][j], af[i], bf[j]);
        }
        __syncthreads();
        if (c + 2 < NC) { LOAD_STAGE(c + 2, c & 1); CP_COMMIT(); }
    }
#undef LOAD_STAGE

    // epilogue
#pragma unroll
    for (int i = 0; i < 4; i++) {
        const int r0 = m0 + wm * 64 + i * 16 + g;
        const int r1 = r0 + 8;
#pragma unroll
        for (int j = 0; j < 4; j++) {
            const int col = n0 + wn * 32 + j * 8 + c4 * 2;
            float v0 = acc[i][j][0], v1 = acc[i][j][1];
            float v2 = acc[i][j][2], v3 = acc[i][j][3];
            if (bias) {
                const float b0 = bias[col], b1 = bias[col + 1];
                v0 += b0; v1 += b1; v2 += b0; v3 += b1;
            }
            if (RELU) {
                v0 = fmaxf(v0, 0.f); v1 = fmaxf(v1, 0.f);
                v2 = fmaxf(v2, 0.f); v3 = fmaxf(v3, 0.f);
            }
            if (RESID) {
                const float2 ra = *(const float2*)&R[(size_t)r0 * N + col];
                const float2 rb2 = *(const float2*)&R[(size_t)r1 * N + col];
                v0 += ra.x; v1 += ra.y; v2 += rb2.x; v3 += rb2.y;
            }
            *(float2*)&C[(size_t)r0 * N + col] = make_float2(v0, v1);
            *(float2*)&C[(size_t)r1 * N + col] = make_float2(v2, v3);
        }
    }
}

// ---------------- transpose: out[N,K] = in[K,N]^T ----------------------------
__global__ __launch_bounds__(256) void transpose_k(
    const float* __restrict__ in, float* __restrict__ out, int Kd, int Nd)
{
    __shared__ float t[32][33];
    const int n0 = blockIdx.x * 32, k0 = blockIdx.y * 32;
    const int x = threadIdx.x, y = threadIdx.y;
#pragma unroll
    for (int dy = 0; dy < 32; dy += 8)
        t[y + dy][x] = in[(size_t)(k0 + y + dy) * Nd + n0 + x];
    __syncthreads();
#pragma unroll
    for (int dy = 0; dy < 32; dy += 8)
        out[(size_t)(n0 + y + dy) * Kd + k0 + x] = t[x][y + dy];
}

// ---------------- LayerNorm ---------------------------------------------------
__global__ __launch_bounds__(256) void ln_kernel(
    const float* __restrict__ X, const float* __restrict__ g,
    const float* __restrict__ b, float* __restrict__ Y)
{
    const int row = blockIdx.x;
    const float* xr = X + (size_t)row * Dn;
    float* yr = Y + (size_t)row * Dn;
    const int tid = threadIdx.x;

    float v[3];
    float s = 0.f, s2 = 0.f;
#pragma unroll
    for (int i = 0; i < 3; i++) {
        float t = xr[tid + 256 * i];
        v[i] = t; s += t; s2 += t * t;
    }
#pragma unroll
    for (int o = 16; o > 0; o >>= 1) {
        s  += __shfl_down_sync(0xffffffffu, s,  o);
        s2 += __shfl_down_sync(0xffffffffu, s2, o);
    }
    __shared__ float rs[8], rs2[8];
    __shared__ float sh_mean, sh_inv;
    const int w = tid >> 5, ln = tid & 31;
    if (ln == 0) { rs[w] = s; rs2[w] = s2; }
    __syncthreads();
    if (tid == 0) {
        float a = 0.f, a2 = 0.f;
#pragma unroll
        for (int i = 0; i < 8; i++) { a += rs[i]; a2 += rs2[i]; }
        float m = a * (1.f / Dn);
        float var = a2 * (1.f / Dn) - m * m;
        sh_mean = m;
        sh_inv = rsqrtf(var + 1e-5f);
    }
    __syncthreads();
    const float m = sh_mean, inv = sh_inv;
#pragma unroll
    for (int i = 0; i < 3; i++) {
        int c = tid + 256 * i;
        yr[c] = (v[i] - m) * inv * g[c] + b[c];
    }
}

// ============ Tensor-core flash attention (tf32 mma, online softmax) ========
#define APAD 68
#define VPAD 72
#define ATT_SMEM ((128*APAD + 64*APAD + 64*VPAD) * 4 + 64 * 4)

__global__ void __launch_bounds__(256, 2) attn_mma_kernel(
    const float* __restrict__ QKV, const int* __restrict__ msk,
    float* __restrict__ O)
{
    extern __shared__ __align__(16) float sm[];
    float* Ps = sm;                       // [128][APAD]
    float* Ks = sm + 128 * APAD;          // [64][APAD]
    float* Vs = Ks + 64 * APAD;           // [64][VPAD]
    int*   ms = (int*)(Vs + 64 * VPAD);   // [64]
    uint32_t* Pu = (uint32_t*)Ps;
    uint32_t* Ku = (uint32_t*)Ks;
    uint32_t* Vu = (uint32_t*)Vs;
    const uint32_t sb = smem_to_u32(sm);

    const int qt = blockIdx.x, h = blockIdx.y, b = blockIdx.z;
    const int tid = threadIdx.x;
    const int w = tid >> 5, lane = tid & 31;
    const int g = lane >> 2, c4 = lane & 3;
    const size_t base  = (size_t)b * Tn * QKVs + (size_t)h * HSn;
    const size_t obase = (size_t)b * Tn * Dn + (size_t)h * HSn;
    const int q0 = qt * 128;

    // ---- stage Q (raw f32) via cp.async
#pragma unroll
    for (int e = 0; e < 8; e++) {
        int idx = tid + e * 256;
        int r = idx >> 4, cc = (idx & 15) * 4;
        cp16(sb + (uint32_t)(r * APAD + cc) * 4,
             &QKV[base + (size_t)(q0 + r) * QKVs + cc]);
    }
    CP_COMMIT(); CP_WAIT(0);
    __syncthreads();

    // ---- Q fragments -> registers
    uint32_t qf[8][4];
#pragma unroll
    for (int kc = 0; kc < 8; kc++) {
        int r0 = (w * 16 + g) * APAD + kc * 8 + c4;
        qf[kc][0] = Pu[r0];
        qf[kc][1] = Pu[r0 + 8 * APAD];
        qf[kc][2] = Pu[r0 + 4];
        qf[kc][3] = Pu[r0 + 8 * APAD + 4];
    }
    __syncthreads();  // Ps now free for P

    float m0r = -1e30f, m1r = -1e30f, l0 = 0.f, l1 = 0.f;
    float o[8][4];
#pragma unroll
    for (int nt = 0; nt < 8; nt++)
#pragma unroll
        for (int e = 0; e < 4; e++) o[nt][e] = 0.f;

    const float rsc = 0.03608439182435161f;  // 768^-0.5 (embed_dim, not hs)
    const uint32_t kbs = sb + 128 * APAD * 4;
    const uint32_t vbs = kbs + 64 * APAD * 4;

    for (int kt = 0; kt < Tn; kt += 64) {
        // ---- stage K, V (raw f32) via cp.async
#pragma unroll
        for (int e = 0; e < 4; e++) {
            int idx = tid + e * 256;
            int r = idx >> 4, cc = (idx & 15) * 4;
            size_t gi = base + (size_t)(kt + r) * QKVs + cc;
            cp16(kbs + (uint32_t)(r * APAD + cc) * 4, &QKV[gi + 768]);
            cp16(vbs + (uint32_t)(r * VPAD + cc) * 4, &QKV[gi + 1536]);
        }
        if (tid < 64) ms[tid] = msk[b * Tn + kt + tid];
        CP_COMMIT(); CP_WAIT(0);
        __syncthreads();

        // ---- S = Q K^T
        float s[8][4];
#pragma unroll
        for (int nt = 0; nt < 8; nt++)
#pragma unroll
            for (int e = 0; e < 4; e++) s[nt][e] = 0.f;
#pragma unroll
        for (int kc = 0; kc < 8; kc++) {
#pragma unroll
            for (int nt = 0; nt < 8; nt++) {
                uint32_t bf[2];
                int ka = (nt * 8 + g) * APAD + kc * 8 + c4;
                bf[0] = Ku[ka];
                bf[1] = Ku[ka + 4];
                mma8(s[nt], qf[kc], bf);
            }
        }

        // ---- mask + scale + online softmax
        float mx0 = -1e30f, mx1 = -1e30f;
#pragma unroll
        for (int nt = 0; nt < 8; nt++) {
            const int mk0 = ms[nt * 8 + 2 * c4], mk1 = ms[nt * 8 + 2 * c4 + 1];
            s[nt][0] = mk0 ? s[nt][0] * rsc : -1e30f;
            s[nt][1] = mk1 ? s[nt][1] * rsc : -1e30f;
            s[nt][2] = mk0 ? s[nt][2] * rsc : -1e30f;
            s[nt][3] = mk1 ? s[nt][3] * rsc : -1e30f;
            mx0 = fmaxf(mx0, fmaxf(s[nt][0], s[nt][1]));
            mx1 = fmaxf(mx1, fmaxf(s[nt][2], s[nt][3]));
        }
        mx0 = fmaxf(mx0, __shfl_xor_sync(0xffffffffu, mx0, 1));
        mx0 = fmaxf(mx0, __shfl_xor_sync(0xffffffffu, mx0, 2));
        mx1 = fmaxf(mx1, __shfl_xor_sync(0xffffffffu, mx1, 1));
        mx1 = fmaxf(mx1, __shfl_xor_sync(0xffffffffu, mx1, 2));

        const float mn0 = fmaxf(m0r, mx0), mn1 = fmaxf(m1r, mx1);
        const float a0 = __expf(m0r - mn0), a1 = __expf(m1r - mn1);
        float rs0 = 0.f, rs1 = 0.f;
#pragma unroll
        for (int nt = 0; nt < 8; nt++) {
            float p0 = __expf(s[nt][0] - mn0);
            float p1 = __expf(s[nt][1] - mn0);
            float p2 = __expf(s[nt][2] - mn1);
            float p3 = __expf(s[nt][3] - mn1);
            rs0 += p0 + p1;
            rs1 += p2 + p3;
            int pa = (w * 16 + g) * APAD + nt * 8 + 2 * c4;
            Pu[pa]                = __float_as_uint(p0);
            Pu[pa + 1]            = __float_as_uint(p1);
            Pu[pa + 8 * APAD]     = __float_as_uint(p2);
            Pu[pa + 8 * APAD + 1] = __float_as_uint(p3);
        }
        rs0 += __shfl_xor_sync(0xffffffffu, rs0, 1);
        rs0 += __shfl_xor_sync(0xffffffffu, rs0, 2);
        rs1 += __shfl_xor_sync(0xffffffffu, rs1, 1);
        rs1 += __shfl_xor_sync(0xffffffffu, rs1, 2);
        l0 = l0 * a0 + rs0;
        l1 = l1 * a1 + rs1;
        m0r = mn0; m1r = mn1;
#pragma unroll
        for (int nt = 0; nt < 8; nt++) {
            o[nt][0] *= a0; o[nt][1] *= a0;
            o[nt][2] *= a1; o[nt][3] *= a1;
        }
        __syncwarp();

        // ---- O += P V
#pragma unroll
        for (int kc = 0; kc < 8; kc++) {
            uint32_t pf[4];
            int pa = (w * 16 + g) * APAD + kc * 8 + c4;
            pf[0] = Pu[pa];
            pf[1] = Pu[pa + 8 * APAD];
            pf[2] = Pu[pa + 4];
            pf[3] = Pu[pa + 8 * APAD + 4];
#pragma unroll
            for (int nt = 0; nt < 8; nt++) {
                uint32_t bf[2];
                int va = (kc * 8 + c4) * VPAD + nt * 8 + g;
                bf[0] = Vu[va];
                bf[1] = Vu[va + 4 * VPAD];
                mma8(o[nt], pf, bf);
            }
        }
        __syncthreads();
    }

    // ---- epilogue
    const float il0 = 1.f / l0, il1 = 1.f / l1;
    const int r0 = q0 + w * 16 + g;
#pragma unroll
    for (int nt = 0; nt < 8; nt++) {
        const int col = nt * 8 + 2 * c4;
        *(float2*)&O[obase + (size_t)r0 * Dn + col] =
            make_float2(o[nt][0] * il0, o[nt][1] * il0);
        *(float2*)&O[obase + (size_t)(r0 + 8) * Dn + col] =
            make_float2(o[nt][2] * il1, o[nt][3] * il1);
    }
}

// ---------------- launch ----------------------------------------------------
extern "C" void kernel_launch(void* const* d_in, const int* in_sizes, int n_in,
                              void* d_out, int out_size)
{
    (void)in_sizes; (void)n_in; (void)out_size;
    const float* x    = (const float*)d_in[0];
    const int*   mask = (const int*)d_in[1];
    const float* Wq   = (const float*)d_in[2];
    const float* Wk   = (const float*)d_in[3];
    const float* Wv   = (const float*)d_in[4];
    const float* Wo   = (const float*)d_in[5];
    const float* bo   = (const float*)d_in[6];
    const float* l1g  = (const float*)d_in[7];
    const float* l1b  = (const float*)d_in[8];
    const float* l2g  = (const float*)d_in[9];
    const float* l2b  = (const float*)d_in[10];
    const float* W1   = (const float*)d_in[11];
    const float* b1   = (const float*)d_in[12];
    const float* W2   = (const float*)d_in[13];
    const float* b2   = (const float*)d_in[14];
    float* out = (float*)d_out;

    float *ph, *pqkv, *pa, *pf, *pw;
    cudaGetSymbolAddress((void**)&ph, g_h);
    cudaGetSymbolAddress((void**)&pqkv, g_qkv);
    cudaGetSymbolAddress((void**)&pa, g_att);
    cudaGetSymbolAddress((void**)&pf, g_ff);
    cudaGetSymbolAddress((void**)&pw, g_wt);

    float* wqkvT = pw;                       // [2304][768] (wq|wk|wv stacked)
    float* woT   = pw + 3 * 589824;
    float* w1T   = pw + 4 * 589824;
    float* w2T   = pw + 4 * 589824 + 2359296;

    cudaFuncSetAttribute(attn_mma_kernel,
                         cudaFuncAttributeMaxDynamicSharedMemorySize, ATT_SMEM);
    cudaFuncSetAttribute(mgemm_k<false, false>,
                         cudaFuncAttributeMaxDynamicSharedMemorySize, GEMM_SMEM);
    cudaFuncSetAttribute(mgemm_k<false, true>,
                         cudaFuncAttributeMaxDynamicSharedMemorySize, GEMM_SMEM);
    cudaFuncSetAttribute(mgemm_k<true, false>,
                         cudaFuncAttributeMaxDynamicSharedMemorySize, GEMM_SMEM);

    // 0) transpose weights to [N,K] K-major
    dim3 tb(32, 8);
    transpose_k<<<dim3(Dn / 32, Dn / 32), tb>>>(Wq, wqkvT, Dn, Dn);
    transpose_k<<<dim3(Dn / 32, Dn / 32), tb>>>(Wk, wqkvT + 589824, Dn, Dn);
    transpose_k<<<dim3(Dn / 32, Dn / 32), tb>>>(Wv, wqkvT + 2 * 589824, Dn, Dn);
    transpose_k<<<dim3(Dn / 32, Dn / 32), tb>>>(Wo, woT, Dn, Dn);
    transpose_k<<<dim3(DFFn / 32, Dn / 32), tb>>>(W1, w1T, Dn, DFFn);
    transpose_k<<<dim3(Dn / 32, DFFn / 32), tb>>>(W2, w2T, DFFn, Dn);

    // 1) h = ln1(x)
    ln_kernel<<<BTn, 256>>>(x, l1g, l1b, ph);

    // 2) qkv = h @ [Wq|Wk|Wv]
    mgemm_k<false, false><<<dim3(QKVs / 128, BTn / 128), 256, GEMM_SMEM>>>(
        ph, wqkvT, nullptr, nullptr, pqkv, BTn, QKVs, Dn);

    // 3) tensor-core flash attention
    attn_mma_kernel<<<dim3(Tn / 128, Hn, Bq), 256, ATT_SMEM>>>(pqkv, mask, pa);

    // 4) x2 = x + att @ Wo + bo  -> d_out
    mgemm_k<false, true><<<dim3(Dn / 128, BTn / 128), 256, GEMM_SMEM>>>(
        pa, woT, bo, x, out, BTn, Dn, Dn);

    // 5) h2 = ln2(x2)
    ln_kernel<<<BTn, 256>>>(out, l2g, l2b, ph);

    // 6) ff = relu(h2 @ W1 + b1)
    mgemm_k<true, false><<<dim3(DFFn / 128, BTn / 128), 256, GEMM_SMEM>>>(
        ph, w1T, b1, nullptr, pf, BTn, DFFn, Dn);

    // 7) out = x2 + ff @ W2 + b2
    mgemm_k<false, true><<<dim3(Dn / 128, BTn / 128), 256, GEMM_SMEM>>>(
        pf, w2T, b2, out, out, BTn, Dn, DFFn);
}

// round 6
// speedup vs baseline: 3.7449x; 1.0007x over previous
#include <cuda_runtime.h>
#include <cstdint>

#define Bq 2
#define Tn 2048
#define Dn 768
#define Hn 12
#define HSn 64
#define BTn (Bq*Tn)
#define DFFn (4*Dn)
#define QKVs 2304

// ---------------- scratch (static device globals; no allocations) -----------
__device__ float g_h[(size_t)BTn*Dn];       // ln1(x) / ln2(x2)
__device__ float g_qkv[(size_t)BTn*QKVs];   // [q|k|v] interleaved per row
__device__ float g_att[(size_t)BTn*Dn];     // attention output (head-concat)
__device__ float g_ff[(size_t)BTn*DFFn];    // relu(h2 W1 + b1)
__device__ float g_wt[4*589824 + 2*2359296];

// ---------------- helpers ----------------------------------------------------
__device__ __forceinline__ uint32_t smem_to_u32(const void* p) {
    uint32_t a;
    asm("{ .reg .u64 t; cvta.to.shared.u64 t, %1; cvt.u32.u64 %0, t; }"
        : "=r"(a) : "l"(p));
    return a;
}
__device__ __forceinline__ void cp16(uint32_t s, const float* g) {
    asm volatile("cp.async.cg.shared.global [%0], [%1], 16;" :: "r"(s), "l"(g));
}
#define CP_COMMIT() asm volatile("cp.async.commit_group;" ::: "memory")
#define CP_WAIT(n)  asm volatile("cp.async.wait_group %0;" :: "n"(n) : "memory")

__device__ __forceinline__ uint32_t f2tf(float f) {
    uint32_t r;
    asm("cvt.rna.tf32.f32 %0, %1;" : "=r"(r) : "f"(f));
    return r;
}
__device__ __forceinline__ float rnd_tf(float f) { return __uint_as_float(f2tf(f)); }

// raw f32 bits into tf32 mma (operands are pre-rounded by producers)
__device__ __forceinline__ void mma8(float* d, const uint32_t* a, const uint32_t* b) {
    asm volatile(
        "mma.sync.aligned.m16n8k8.row.col.f32.tf32.tf32.f32 "
        "{%0,%1,%2,%3}, {%4,%5,%6,%7}, {%8,%9}, {%0,%1,%2,%3};"
        : "+f"(d[0]), "+f"(d[1]), "+f"(d[2]), "+f"(d[3])
        : "r"(a[0]), "r"(a[1]), "r"(a[2]), "r"(a[3]), "r"(b[0]), "r"(b[1]));
}

// ============== tf32 mma GEMM (128x128 tile): C = A[M,K] * BT[N,K]^T =========
// BK=32, 256 threads (8 warps 2x4), warp tile 64x32, 3-stage cp.async,
// one __syncthreads per chunk. smem row-major [m][36] (pad 4), conflict-free.
#define GSTRIDE 36
#define GSTAGE  (128*GSTRIDE)             // u32 per matrix per stage
#define GEMM_SMEM (3*2*GSTAGE*4)          // 110592 bytes

template<bool RELU, bool RESID, bool CVT>
__global__ __launch_bounds__(256) void mgemm_k(
    const float* __restrict__ A, const float* __restrict__ BT,
    const float* __restrict__ bias, const float* __restrict__ R,
    float* __restrict__ C, int M, int N, int K)
{
    extern __shared__ __align__(16) uint32_t smu[];
    const uint32_t sb = smem_to_u32(smu);

    const int tid = threadIdx.x;
    const int wid = tid >> 5, lane = tid & 31;
    const int g = lane >> 2, c4 = lane & 3;
    const int wm = wid & 1, wn = wid >> 1;
    const int m0 = blockIdx.y * 128, n0 = blockIdx.x * 128;

    const int rb = tid >> 3, cl = (tid & 7) * 4;
    const float* Abase = A  + (size_t)(m0 + rb) * K + cl;
    const float* Bbase = BT + (size_t)(n0 + rb) * K + cl;

    float acc[4][4][4];
#pragma unroll
    for (int i = 0; i < 4; i++)
#pragma unroll
        for (int j = 0; j < 4; j++)
#pragma unroll
            for (int e = 0; e < 4; e++) acc[i][j][e] = 0.f;

    const int NC = K >> 5;

#define LOAD_STAGE(c_, s_) do { \
    const uint32_t _da = sb + (uint32_t)((s_) * 2 * GSTAGE) * 4u; \
    const uint32_t _db = _da + GSTAGE * 4u; \
    const int _ko = (c_) * 32; \
    _Pragma("unroll") \
    for (int _e = 0; _e < 4; _e++) { \
        const uint32_t _so = (uint32_t)(((_e * 32 + rb) * GSTRIDE + cl) * 4); \
        const size_t _go = (size_t)(_e * 32) * K + _ko; \
        cp16(_da + _so, Abase + _go); \
        cp16(_db + _so, Bbase + _go); \
    } } while (0)

    LOAD_STAGE(0, 0); CP_COMMIT();
    if (NC > 1) { LOAD_STAGE(1, 1); CP_COMMIT(); }

    for (int c = 0; c < NC; c++) {
        if (c + 1 < NC) { CP_WAIT(1); } else { CP_WAIT(0); }
        __syncthreads();
        if (c + 2 < NC) { LOAD_STAGE(c + 2, (c + 2) % 3); CP_COMMIT(); }

        const uint32_t* Asp = smu + (c % 3) * 2 * GSTAGE;
        const uint32_t* Bsp = Asp + GSTAGE;

#pragma unroll
        for (int s = 0; s < 4; s++) {
            const int kk = s * 8 + c4;
            uint32_t af[4][4], bf[4][2];
#pragma unroll
            for (int i = 0; i < 4; i++) {
                const int mm = (wm * 64 + i * 16 + g) * GSTRIDE;
                af[i][0] = Asp[mm + kk];
                af[i][1] = Asp[mm + 8 * GSTRIDE + kk];
                af[i][2] = Asp[mm + kk + 4];
                af[i][3] = Asp[mm + 8 * GSTRIDE + kk + 4];
            }
#pragma unroll
            for (int j = 0; j < 4; j++) {
                const int nn = (wn * 32 + j * 8 + g) * GSTRIDE;
                bf[j][0] = Bsp[nn + kk];
                bf[j][1] = Bsp[nn + kk + 4];
            }
#pragma unroll
            for (int i = 0; i < 4; i++)
#pragma unroll
                for (int j = 0; j < 4; j++)
                    mma8(acc[i][j], af[i], bf[j]);
        }
    }
#undef LOAD_STAGE

#pragma unroll
    for (int i = 0; i < 4; i++) {
        const int r0 = m0 + wm * 64 + i * 16 + g;
        const int r1 = r0 + 8;
#pragma unroll
        for (int j = 0; j < 4; j++) {
            const int col = n0 + wn * 32 + j * 8 + c4 * 2;
            float v0 = acc[i][j][0], v1 = acc[i][j][1];
            float v2 = acc[i][j][2], v3 = acc[i][j][3];
            if (bias) {
                const float b0 = bias[col], b1 = bias[col + 1];
                v0 += b0; v1 += b1; v2 += b0; v3 += b1;
            }
            if (RELU) {
                v0 = fmaxf(v0, 0.f); v1 = fmaxf(v1, 0.f);
                v2 = fmaxf(v2, 0.f); v3 = fmaxf(v3, 0.f);
            }
            if (RESID) {
                const float2 ra = *(const float2*)&R[(size_t)r0 * N + col];
                const float2 rb2 = *(const float2*)&R[(size_t)r1 * N + col];
                v0 += ra.x; v1 += ra.y; v2 += rb2.x; v3 += rb2.y;
            }
            if (CVT) {
                v0 = rnd_tf(v0); v1 = rnd_tf(v1);
                v2 = rnd_tf(v2); v3 = rnd_tf(v3);
            }
            *(float2*)&C[(size_t)r0 * N + col] = make_float2(v0, v1);
            *(float2*)&C[(size_t)r1 * N + col] = make_float2(v2, v3);
        }
    }
}

// ============== tf32 mma GEMM (64x128 tile) — for tail-bound Wo/W2 ==========
// 256 threads, 8 warps 2(m)x4(n), warp tile 32x32, 3-stage cp.async.
#define G64STAGE ((64+128)*GSTRIDE)       // u32 per stage (A then B)
#define GEMM64_SMEM (3*G64STAGE*4)        // 82944 bytes

template<bool RELU, bool RESID, bool CVT>
__global__ __launch_bounds__(256) void mgemm64_k(
    const float* __restrict__ A, const float* __restrict__ BT,
    const float* __restrict__ bias, const float* __restrict__ R,
    float* __restrict__ C, int M, int N, int K)
{
    extern __shared__ __align__(16) uint32_t smu[];
    const uint32_t sb = smem_to_u32(smu);

    const int tid = threadIdx.x;
    const int wid = tid >> 5, lane = tid & 31;
    const int g = lane >> 2, c4 = lane & 3;
    const int wm = wid & 1, wn = wid >> 1;
    const int m0 = blockIdx.y * 64, n0 = blockIdx.x * 128;

    const int rb = tid >> 3, cl = (tid & 7) * 4;   // rb 0..31
    const float* Abase = A  + (size_t)(m0 + rb) * K + cl;
    const float* Bbase = BT + (size_t)(n0 + rb) * K + cl;

    float acc[2][4][4];
#pragma unroll
    for (int i = 0; i < 2; i++)
#pragma unroll
        for (int j = 0; j < 4; j++)
#pragma unroll
            for (int e = 0; e < 4; e++) acc[i][j][e] = 0.f;

    const int NC = K >> 5;

#define LOAD_STAGE64(c_, s_) do { \
    const uint32_t _da = sb + (uint32_t)((s_) * G64STAGE) * 4u; \
    const uint32_t _db = _da + 64u * GSTRIDE * 4u; \
    const int _ko = (c_) * 32; \
    _Pragma("unroll") \
    for (int _e = 0; _e < 2; _e++) { \
        const uint32_t _so = (uint32_t)(((_e * 32 + rb) * GSTRIDE + cl) * 4); \
        cp16(_da + _so, Abase + (size_t)(_e * 32) * K + _ko); \
    } \
    _Pragma("unroll") \
    for (int _e = 0; _e < 4; _e++) { \
        const uint32_t _so = (uint32_t)(((_e * 32 + rb) * GSTRIDE + cl) * 4); \
        cp16(_db + _so, Bbase + (size_t)(_e * 32) * K + _ko); \
    } } while (0)

    LOAD_STAGE64(0, 0); CP_COMMIT();
    if (NC > 1) { LOAD_STAGE64(1, 1); CP_COMMIT(); }

    for (int c = 0; c < NC; c++) {
        if (c + 1 < NC) { CP_WAIT(1); } else { CP_WAIT(0); }
        __syncthreads();
        if (c + 2 < NC) { LOAD_STAGE64(c + 2, (c + 2) % 3); CP_COMMIT(); }

        const uint32_t* Asp = smu + (c % 3) * G64STAGE;
        const uint32_t* Bsp = Asp + 64 * GSTRIDE;

#pragma unroll
        for (int s = 0; s < 4; s++) {
            const int kk = s * 8 + c4;
            uint32_t af[2][4], bf[4][2];
#pragma unroll
            for (int i = 0; i < 2; i++) {
                const int mm = (wm * 32 + i * 16 + g) * GSTRIDE;
                af[i][0] = Asp[mm + kk];
                af[i][1] = Asp[mm + 8 * GSTRIDE + kk];
                af[i][2] = Asp[mm + kk + 4];
                af[i][3] = Asp[mm + 8 * GSTRIDE + kk + 4];
            }
#pragma unroll
            for (int j = 0; j < 4; j++) {
                const int nn = (wn * 32 + j * 8 + g) * GSTRIDE;
                bf[j][0] = Bsp[nn + kk];
                bf[j][1] = Bsp[nn + kk + 4];
            }
#pragma unroll
            for (int i = 0; i < 2; i++)
#pragma unroll
                for (int j = 0; j < 4; j++)
                    mma8(acc[i][j], af[i], bf[j]);
        }
    }
#undef LOAD_STAGE64

#pragma unroll
    for (int i = 0; i < 2; i++) {
        const int r0 = m0 + wm * 32 + i * 16 + g;
        const int r1 = r0 + 8;
#pragma unroll
        for (int j = 0; j < 4; j++) {
            const int col = n0 + wn * 32 + j * 8 + c4 * 2;
            float v0 = acc[i][j][0], v1 = acc[i][j][1];
            float v2 = acc[i][j][2], v3 = acc[i][j][3];
            if (bias) {
                const float b0 = bias[col], b1 = bias[col + 1];
                v0 += b0; v1 += b1; v2 += b0; v3 += b1;
            }
            if (RELU) {
                v0 = fmaxf(v0, 0.f); v1 = fmaxf(v1, 0.f);
                v2 = fmaxf(v2, 0.f); v3 = fmaxf(v3, 0.f);
            }
            if (RESID) {
                const float2 ra = *(const float2*)&R[(size_t)r0 * N + col];
                const float2 rb2 = *(const float2*)&R[(size_t)r1 * N + col];
                v0 += ra.x; v1 += ra.y; v2 += rb2.x; v3 += rb2.y;
            }
            if (CVT) {
                v0 = rnd_tf(v0); v1 = rnd_tf(v1);
                v2 = rnd_tf(v2); v3 = rnd_tf(v3);
            }
            *(float2*)&C[(size_t)r0 * N + col] = make_float2(v0, v1);
            *(float2*)&C[(size_t)r1 * N + col] = make_float2(v2, v3);
        }
    }
}

// ---------------- transpose (+tf32 round): out[N,K] = round(in[K,N]^T) -------
__global__ __launch_bounds__(256) void transpose_k(
    const float* __restrict__ in, float* __restrict__ out, int Kd, int Nd)
{
    __shared__ float t[32][33];
    const int n0 = blockIdx.x * 32, k0 = blockIdx.y * 32;
    const int x = threadIdx.x, y = threadIdx.y;
#pragma unroll
    for (int dy = 0; dy < 32; dy += 8)
        t[y + dy][x] = in[(size_t)(k0 + y + dy) * Nd + n0 + x];
    __syncthreads();
#pragma unroll
    for (int dy = 0; dy < 32; dy += 8)
        out[(size_t)(n0 + y + dy) * Kd + k0 + x] = rnd_tf(t[x][y + dy]);
}

// ---------------- LayerNorm (output rounded to tf32 grid) --------------------
__global__ __launch_bounds__(256) void ln_kernel(
    const float* __restrict__ X, const float* __restrict__ g,
    const float* __restrict__ b, float* __restrict__ Y)
{
    const int row = blockIdx.x;
    const float* xr = X + (size_t)row * Dn;
    float* yr = Y + (size_t)row * Dn;
    const int tid = threadIdx.x;

    float v[3];
    float s = 0.f, s2 = 0.f;
#pragma unroll
    for (int i = 0; i < 3; i++) {
        float t = xr[tid + 256 * i];
        v[i] = t; s += t; s2 += t * t;
    }
#pragma unroll
    for (int o = 16; o > 0; o >>= 1) {
        s  += __shfl_down_sync(0xffffffffu, s,  o);
        s2 += __shfl_down_sync(0xffffffffu, s2, o);
    }
    __shared__ float rs[8], rs2[8];
    __shared__ float sh_mean, sh_inv;
    const int w = tid >> 5, ln = tid & 31;
    if (ln == 0) { rs[w] = s; rs2[w] = s2; }
    __syncthreads();
    if (tid == 0) {
        float a = 0.f, a2 = 0.f;
#pragma unroll
        for (int i = 0; i < 8; i++) { a += rs[i]; a2 += rs2[i]; }
        float m = a * (1.f / Dn);
        float var = a2 * (1.f / Dn) - m * m;
        sh_mean = m;
        sh_inv = rsqrtf(var + 1e-5f);
    }
    __syncthreads();
    const float m = sh_mean, inv = sh_inv;
#pragma unroll
    for (int i = 0; i < 3; i++) {
        int c = tid + 256 * i;
        yr[c] = rnd_tf((v[i] - m) * inv * g[c] + b[c]);
    }
}

// ============ Tensor-core flash attention (tf32 mma, online softmax) ========
#define APAD 68
#define VPAD 72
#define ATT_SMEM ((128*APAD + 64*APAD + 64*VPAD) * 4 + 64 * 4)

__global__ void __launch_bounds__(256, 2) attn_mma_kernel(
    const float* __restrict__ QKV, const int* __restrict__ msk,
    float* __restrict__ O)
{
    extern __shared__ __align__(16) float sm[];
    float* Ps = sm;                       // [128][APAD]
    float* Ks = sm + 128 * APAD;          // [64][APAD]
    float* Vs = Ks + 64 * APAD;           // [64][VPAD]
    int*   ms = (int*)(Vs + 64 * VPAD);   // [64]
    uint32_t* Pu = (uint32_t*)Ps;
    uint32_t* Ku = (uint32_t*)Ks;
    uint32_t* Vu = (uint32_t*)Vs;
    const uint32_t sb = smem_to_u32(sm);

    const int qt = blockIdx.x, h = blockIdx.y, b = blockIdx.z;
    const int tid = threadIdx.x;
    const int w = tid >> 5, lane = tid & 31;
    const int g = lane >> 2, c4 = lane & 3;
    const size_t base  = (size_t)b * Tn * QKVs + (size_t)h * HSn;
    const size_t obase = (size_t)b * Tn * Dn + (size_t)h * HSn;
    const int q0 = qt * 128;

#pragma unroll
    for (int e = 0; e < 8; e++) {
        int idx = tid + e * 256;
        int r = idx >> 4, cc = (idx & 15) * 4;
        cp16(sb + (uint32_t)(r * APAD + cc) * 4,
             &QKV[base + (size_t)(q0 + r) * QKVs + cc]);
    }
    CP_COMMIT(); CP_WAIT(0);
    __syncthreads();

    uint32_t qf[8][4];
#pragma unroll
    for (int kc = 0; kc < 8; kc++) {
        int r0 = (w * 16 + g) * APAD + kc * 8 + c4;
        qf[kc][0] = Pu[r0];
        qf[kc][1] = Pu[r0 + 8 * APAD];
        qf[kc][2] = Pu[r0 + 4];
        qf[kc][3] = Pu[r0 + 8 * APAD + 4];
    }
    __syncthreads();

    float m0r = -1e30f, m1r = -1e30f, l0 = 0.f, l1 = 0.f;
    float o[8][4];
#pragma unroll
    for (int nt = 0; nt < 8; nt++)
#pragma unroll
        for (int e = 0; e < 4; e++) o[nt][e] = 0.f;

    const float rsc = 0.03608439182435161f;  // 768^-0.5 (embed_dim, not hs)
    const uint32_t kbs = sb + 128 * APAD * 4;
    const uint32_t vbs = kbs + 64 * APAD * 4;

    for (int kt = 0; kt < Tn; kt += 64) {
#pragma unroll
        for (int e = 0; e < 4; e++) {
            int idx = tid + e * 256;
            int r = idx >> 4, cc = (idx & 15) * 4;
            size_t gi = base + (size_t)(kt + r) * QKVs + cc;
            cp16(kbs + (uint32_t)(r * APAD + cc) * 4, &QKV[gi + 768]);
            cp16(vbs + (uint32_t)(r * VPAD + cc) * 4, &QKV[gi + 1536]);
        }
        if (tid < 64) ms[tid] = msk[b * Tn + kt + tid];
        CP_COMMIT(); CP_WAIT(0);
        __syncthreads();

        float s[8][4];
#pragma unroll
        for (int nt = 0; nt < 8; nt++)
#pragma unroll
            for (int e = 0; e < 4; e++) s[nt][e] = 0.f;
#pragma unroll
        for (int kc = 0; kc < 8; kc++) {
#pragma unroll
            for (int nt = 0; nt < 8; nt++) {
                uint32_t bf[2];
                int ka = (nt * 8 + g) * APAD + kc * 8 + c4;
                bf[0] = Ku[ka];
                bf[1] = Ku[ka + 4];
                mma8(s[nt], qf[kc], bf);
            }
        }

        float mx0 = -1e30f, mx1 = -1e30f;
#pragma unroll
        for (int nt = 0; nt < 8; nt++) {
            const int mk0 = ms[nt * 8 + 2 * c4], mk1 = ms[nt * 8 + 2 * c4 + 1];
            s[nt][0] = mk0 ? s[nt][0] * rsc : -1e30f;
            s[nt][1] = mk1 ? s[nt][1] * rsc : -1e30f;
            s[nt][2] = mk0 ? s[nt][2] * rsc : -1e30f;
            s[nt][3] = mk1 ? s[nt][3] * rsc : -1e30f;
            mx0 = fmaxf(mx0, fmaxf(s[nt][0], s[nt][1]));
            mx1 = fmaxf(mx1, fmaxf(s[nt][2], s[nt][3]));
        }
        mx0 = fmaxf(mx0, __shfl_xor_sync(0xffffffffu, mx0, 1));
        mx0 = fmaxf(mx0, __shfl_xor_sync(0xffffffffu, mx0, 2));
        mx1 = fmaxf(mx1, __shfl_xor_sync(0xffffffffu, mx1, 1));
        mx1 = fmaxf(mx1, __shfl_xor_sync(0xffffffffu, mx1, 2));

        const float mn0 = fmaxf(m0r, mx0), mn1 = fmaxf(m1r, mx1);
        const float a0 = __expf(m0r - mn0), a1 = __expf(m1r - mn1);
        float rs0 = 0.f, rs1 = 0.f;
#pragma unroll
        for (int nt = 0; nt < 8; nt++) {
            float p0 = __expf(s[nt][0] - mn0);
            float p1 = __expf(s[nt][1] - mn0);
            float p2 = __expf(s[nt][2] - mn1);
            float p3 = __expf(s[nt][3] - mn1);
            rs0 += p0 + p1;
            rs1 += p2 + p3;
            int pa = (w * 16 + g) * APAD + nt * 8 + 2 * c4;
            Pu[pa]                = __float_as_uint(p0);
            Pu[pa + 1]            = __float_as_uint(p1);
            Pu[pa + 8 * APAD]     = __float_as_uint(p2);
            Pu[pa + 8 * APAD + 1] = __float_as_uint(p3);
        }
        rs0 += __shfl_xor_sync(0xffffffffu, rs0, 1);
        rs0 += __shfl_xor_sync(0xffffffffu, rs0, 2);
        rs1 += __shfl_xor_sync(0xffffffffu, rs1, 1);
        rs1 += __shfl_xor_sync(0xffffffffu, rs1, 2);
        l0 = l0 * a0 + rs0;
        l1 = l1 * a1 + rs1;
        m0r = mn0; m1r = mn1;
#pragma unroll
        for (int nt = 0; nt < 8; nt++) {
            o[nt][0] *= a0; o[nt][1] *= a0;
            o[nt][2] *= a1; o[nt][3] *= a1;
        }
        __syncwarp();

#pragma unroll
        for (int kc = 0; kc < 8; kc++) {
            uint32_t pf[4];
            int pa = (w * 16 + g) * APAD + kc * 8 + c4;
            pf[0] = Pu[pa];
            pf[1] = Pu[pa + 8 * APAD];
            pf[2] = Pu[pa + 4];
            pf[3] = Pu[pa + 8 * APAD + 4];
#pragma unroll
            for (int nt = 0; nt < 8; nt++) {
                uint32_t bf[2];
                int va = (kc * 8 + c4) * VPAD + nt * 8 + g;
                bf[0] = Vu[va];
                bf[1] = Vu[va + 4 * VPAD];
                mma8(o[nt], pf, bf);
            }
        }
        __syncthreads();
    }

    const float il0 = 1.f / l0, il1 = 1.f / l1;
    const int r0 = q0 + w * 16 + g;
#pragma unroll
    for (int nt = 0; nt < 8; nt++) {
        const int col = nt * 8 + 2 * c4;
        *(float2*)&O[obase + (size_t)r0 * Dn + col] =
            make_float2(rnd_tf(o[nt][0] * il0), rnd_tf(o[nt][1] * il0));
        *(float2*)&O[obase + (size_t)(r0 + 8) * Dn + col] =
            make_float2(rnd_tf(o[nt][2] * il1), rnd_tf(o[nt][3] * il1));
    }
}

// ---------------- launch ----------------------------------------------------
extern "C" void kernel_launch(void* const* d_in, const int* in_sizes, int n_in,
                              void* d_out, int out_size)
{
    (void)in_sizes; (void)n_in; (void)out_size;
    const float* x    = (const float*)d_in[0];
    const int*   mask = (const int*)d_in[1];
    const float* Wq   = (const float*)d_in[2];
    const float* Wk   = (const float*)d_in[3];
    const float* Wv   = (const float*)d_in[4];
    const float* Wo   = (const float*)d_in[5];
    const float* bo   = (const float*)d_in[6];
    const float* l1g  = (const float*)d_in[7];
    const float* l1b  = (const float*)d_in[8];
    const float* l2g  = (const float*)d_in[9];
    const float* l2b  = (const float*)d_in[10];
    const float* W1   = (const float*)d_in[11];
    const float* b1   = (const float*)d_in[12];
    const float* W2   = (const float*)d_in[13];
    const float* b2   = (const float*)d_in[14];
    float* out = (float*)d_out;

    float *ph, *pqkv, *pa, *pf, *pw;
    cudaGetSymbolAddress((void**)&ph, g_h);
    cudaGetSymbolAddress((void**)&pqkv, g_qkv);
    cudaGetSymbolAddress((void**)&pa, g_att);
    cudaGetSymbolAddress((void**)&pf, g_ff);
    cudaGetSymbolAddress((void**)&pw, g_wt);

    float* wqkvT = pw;
    float* woT   = pw + 3 * 589824;
    float* w1T   = pw + 4 * 589824;
    float* w2T   = pw + 4 * 589824 + 2359296;

    cudaFuncSetAttribute(attn_mma_kernel,
                         cudaFuncAttributeMaxDynamicSharedMemorySize, ATT_SMEM);
    cudaFuncSetAttribute(mgemm_k<false, false, true>,
                         cudaFuncAttributeMaxDynamicSharedMemorySize, GEMM_SMEM);
    cudaFuncSetAttribute(mgemm_k<true, false, true>,
                         cudaFuncAttributeMaxDynamicSharedMemorySize, GEMM_SMEM);
    cudaFuncSetAttribute(mgemm64_k<false, true, false>,
                         cudaFuncAttributeMaxDynamicSharedMemorySize, GEMM64_SMEM);

    // 0) transpose weights to [N,K] K-major, rounded to tf32 grid
    dim3 tb(32, 8);
    transpose_k<<<dim3(Dn / 32, Dn / 32), tb>>>(Wq, wqkvT, Dn, Dn);
    transpose_k<<<dim3(Dn / 32, Dn / 32), tb>>>(Wk, wqkvT + 589824, Dn, Dn);
    transpose_k<<<dim3(Dn / 32, Dn / 32), tb>>>(Wv, wqkvT + 2 * 589824, Dn, Dn);
    transpose_k<<<dim3(Dn / 32, Dn / 32), tb>>>(Wo, woT, Dn, Dn);
    transpose_k<<<dim3(DFFn / 32, Dn / 32), tb>>>(W1, w1T, Dn, DFFn);
    transpose_k<<<dim3(Dn / 32, DFFn / 32), tb>>>(W2, w2T, DFFn, Dn);

    // 1) h = ln1(x)   (rounded)
    ln_kernel<<<BTn, 256>>>(x, l1g, l1b, ph);

    // 2) qkv = h @ [Wq|Wk|Wv]   (output rounded)
    mgemm_k<false, false, true><<<dim3(QKVs / 128, BTn / 128), 256, GEMM_SMEM>>>(
        ph, wqkvT, nullptr, nullptr, pqkv, BTn, QKVs, Dn);

    // 3) tensor-core flash attention (O rounded)
    attn_mma_kernel<<<dim3(Tn / 128, Hn, Bq), 256, ATT_SMEM>>>(pqkv, mask, pa);

    // 4) x2 = x + att @ Wo + bo  -> d_out  (64-row tiles, full fp32 out)
    mgemm64_k<false, true, false><<<dim3(Dn / 128, BTn / 64), 256, GEMM64_SMEM>>>(
        pa, woT, bo, x, out, BTn, Dn, Dn);

    // 5) h2 = ln2(x2)  (rounded)
    ln_kernel<<<BTn, 256>>>(out, l2g, l2b, ph);

    // 6) ff = relu(h2 @ W1 + b1)  (output rounded)
    mgemm_k<true, false, true><<<dim3(DFFn / 128, BTn / 128), 256, GEMM_SMEM>>>(
        ph, w1T, b1, nullptr, pf, BTn, DFFn, Dn);

    // 7) out = x2 + ff @ W2 + b2  (64-row tiles, full fp32 out)
    mgemm64_k<false, true, false><<<dim3(Dn / 128, BTn / 64), 256, GEMM64_SMEM>>>(
        pf, w2T, b2, out, out, BTn, Dn, DFFn);
}

// round 7
// speedup vs baseline: 4.0699x; 1.0868x over previous
#include <cuda_runtime.h>
#include <cstdint>

#define Bq 2
#define Tn 2048
#define Dn 768
#define Hn 12
#define HSn 64
#define BTn (Bq*Tn)
#define DFFn (4*Dn)
#define QKVs 2304

// ---------------- scratch (static device globals; no allocations) -----------
__device__ float g_h[(size_t)BTn*Dn];       // ln1(x) / ln2(x2)
__device__ float g_qkv[(size_t)BTn*QKVs];   // [q|k|v] interleaved per row
__device__ float g_att[(size_t)BTn*Dn];     // attention output (head-concat)
__device__ float g_ff[(size_t)BTn*DFFn];    // relu(h2 W1 + b1)
__device__ float g_wt[4*589824 + 2*2359296];

// ---------------- helpers ----------------------------------------------------
__device__ __forceinline__ uint32_t smem_to_u32(const void* p) {
    uint32_t a;
    asm("{ .reg .u64 t; cvta.to.shared.u64 t, %1; cvt.u32.u64 %0, t; }"
        : "=r"(a) : "l"(p));
    return a;
}
__device__ __forceinline__ void cp16(uint32_t s, const float* g) {
    asm volatile("cp.async.cg.shared.global [%0], [%1], 16;" :: "r"(s), "l"(g));
}
#define CP_COMMIT() asm volatile("cp.async.commit_group;" ::: "memory")
#define CP_WAIT(n)  asm volatile("cp.async.wait_group %0;" :: "n"(n) : "memory")

__device__ __forceinline__ uint32_t f2tf(float f) {
    uint32_t r;
    asm("cvt.rna.tf32.f32 %0, %1;" : "=r"(r) : "f"(f));
    return r;
}
__device__ __forceinline__ float rnd_tf(float f) { return __uint_as_float(f2tf(f)); }

// raw f32 bits into tf32 mma (operands are pre-rounded by producers)
__device__ __forceinline__ void mma8(float* d, const uint32_t* a, const uint32_t* b) {
    asm volatile(
        "mma.sync.aligned.m16n8k8.row.col.f32.tf32.tf32.f32 "
        "{%0,%1,%2,%3}, {%4,%5,%6,%7}, {%8,%9}, {%0,%1,%2,%3};"
        : "+f"(d[0]), "+f"(d[1]), "+f"(d[2]), "+f"(d[3])
        : "r"(a[0]), "r"(a[1]), "r"(a[2]), "r"(a[3]), "r"(b[0]), "r"(b[1]));
}

// ============== tf32 mma GEMM (128x128 tile): C = A[M,K] * BT[N,K]^T =========
// BK=32, 256 threads (8 warps 2x4), warp tile 64x32, 3-stage cp.async,
// one __syncthreads per chunk, forced 2 CTAs/SM.
#define GSTRIDE 36
#define GSTAGE  (128*GSTRIDE)
#define GEMM_SMEM (3*2*GSTAGE*4)          // 110592 bytes

template<bool RELU, bool RESID, bool CVT>
__global__ void __launch_bounds__(256, 2) mgemm_k(
    const float* __restrict__ A, const float* __restrict__ BT,
    const float* __restrict__ bias, const float* __restrict__ R,
    float* __restrict__ C, int M, int N, int K)
{
    extern __shared__ __align__(16) uint32_t smu[];
    const uint32_t sb = smem_to_u32(smu);

    const int tid = threadIdx.x;
    const int wid = tid >> 5, lane = tid & 31;
    const int g = lane >> 2, c4 = lane & 3;
    const int wm = wid & 1, wn = wid >> 1;
    const int m0 = blockIdx.y * 128, n0 = blockIdx.x * 128;

    const int rb = tid >> 3, cl = (tid & 7) * 4;
    const float* Abase = A  + (size_t)(m0 + rb) * K + cl;
    const float* Bbase = BT + (size_t)(n0 + rb) * K + cl;

    float acc[4][4][4];
#pragma unroll
    for (int i = 0; i < 4; i++)
#pragma unroll
        for (int j = 0; j < 4; j++)
#pragma unroll
            for (int e = 0; e < 4; e++) acc[i][j][e] = 0.f;

    const int NC = K >> 5;

#define LOAD_STAGE(c_, s_) do { \
    const uint32_t _da = sb + (uint32_t)((s_) * 2 * GSTAGE) * 4u; \
    const uint32_t _db = _da + GSTAGE * 4u; \
    const int _ko = (c_) * 32; \
    _Pragma("unroll") \
    for (int _e = 0; _e < 4; _e++) { \
        const uint32_t _so = (uint32_t)(((_e * 32 + rb) * GSTRIDE + cl) * 4); \
        const size_t _go = (size_t)(_e * 32) * K + _ko; \
        cp16(_da + _so, Abase + _go); \
        cp16(_db + _so, Bbase + _go); \
    } } while (0)

    LOAD_STAGE(0, 0); CP_COMMIT();
    if (NC > 1) { LOAD_STAGE(1, 1); CP_COMMIT(); }

    for (int c = 0; c < NC; c++) {
        if (c + 1 < NC) { CP_WAIT(1); } else { CP_WAIT(0); }
        __syncthreads();
        if (c + 2 < NC) { LOAD_STAGE(c + 2, (c + 2) % 3); CP_COMMIT(); }

        const uint32_t* Asp = smu + (c % 3) * 2 * GSTAGE;
        const uint32_t* Bsp = Asp + GSTAGE;

#pragma unroll
        for (int s = 0; s < 4; s++) {
            const int kk = s * 8 + c4;
            uint32_t af[4][4], bf[4][2];
#pragma unroll
            for (int i = 0; i < 4; i++) {
                const int mm = (wm * 64 + i * 16 + g) * GSTRIDE;
                af[i][0] = Asp[mm + kk];
                af[i][1] = Asp[mm + 8 * GSTRIDE + kk];
                af[i][2] = Asp[mm + kk + 4];
                af[i][3] = Asp[mm + 8 * GSTRIDE + kk + 4];
            }
#pragma unroll
            for (int j = 0; j < 4; j++) {
                const int nn = (wn * 32 + j * 8 + g) * GSTRIDE;
                bf[j][0] = Bsp[nn + kk];
                bf[j][1] = Bsp[nn + kk + 4];
            }
#pragma unroll
            for (int i = 0; i < 4; i++)
#pragma unroll
                for (int j = 0; j < 4; j++)
                    mma8(acc[i][j], af[i], bf[j]);
        }
    }
#undef LOAD_STAGE

#pragma unroll
    for (int i = 0; i < 4; i++) {
        const int r0 = m0 + wm * 64 + i * 16 + g;
        const int r1 = r0 + 8;
#pragma unroll
        for (int j = 0; j < 4; j++) {
            const int col = n0 + wn * 32 + j * 8 + c4 * 2;
            float v0 = acc[i][j][0], v1 = acc[i][j][1];
            float v2 = acc[i][j][2], v3 = acc[i][j][3];
            if (bias) {
                const float b0 = bias[col], b1 = bias[col + 1];
                v0 += b0; v1 += b1; v2 += b0; v3 += b1;
            }
            if (RELU) {
                v0 = fmaxf(v0, 0.f); v1 = fmaxf(v1, 0.f);
                v2 = fmaxf(v2, 0.f); v3 = fmaxf(v3, 0.f);
            }
            if (RESID) {
                const float2 ra = *(const float2*)&R[(size_t)r0 * N + col];
                const float2 rb2 = *(const float2*)&R[(size_t)r1 * N + col];
                v0 += ra.x; v1 += ra.y; v2 += rb2.x; v3 += rb2.y;
            }
            if (CVT) {
                v0 = rnd_tf(v0); v1 = rnd_tf(v1);
                v2 = rnd_tf(v2); v3 = rnd_tf(v3);
            }
            *(float2*)&C[(size_t)r0 * N + col] = make_float2(v0, v1);
            *(float2*)&C[(size_t)r1 * N + col] = make_float2(v2, v3);
        }
    }
}

// ============== tf32 mma GEMM (64x128 tile) — for tail-bound Wo/W2 ==========
#define G64STAGE ((64+128)*GSTRIDE)
#define GEMM64_SMEM (3*G64STAGE*4)        // 82944 bytes

template<bool RELU, bool RESID, bool CVT>
__global__ void __launch_bounds__(256, 2) mgemm64_k(
    const float* __restrict__ A, const float* __restrict__ BT,
    const float* __restrict__ bias, const float* __restrict__ R,
    float* __restrict__ C, int M, int N, int K)
{
    extern __shared__ __align__(16) uint32_t smu[];
    const uint32_t sb = smem_to_u32(smu);

    const int tid = threadIdx.x;
    const int wid = tid >> 5, lane = tid & 31;
    const int g = lane >> 2, c4 = lane & 3;
    const int wm = wid & 1, wn = wid >> 1;
    const int m0 = blockIdx.y * 64, n0 = blockIdx.x * 128;

    const int rb = tid >> 3, cl = (tid & 7) * 4;
    const float* Abase = A  + (size_t)(m0 + rb) * K + cl;
    const float* Bbase = BT + (size_t)(n0 + rb) * K + cl;

    float acc[2][4][4];
#pragma unroll
    for (int i = 0; i < 2; i++)
#pragma unroll
        for (int j = 0; j < 4; j++)
#pragma unroll
            for (int e = 0; e < 4; e++) acc[i][j][e] = 0.f;

    const int NC = K >> 5;

#define LOAD_STAGE64(c_, s_) do { \
    const uint32_t _da = sb + (uint32_t)((s_) * G64STAGE) * 4u; \
    const uint32_t _db = _da + 64u * GSTRIDE * 4u; \
    const int _ko = (c_) * 32; \
    _Pragma("unroll") \
    for (int _e = 0; _e < 2; _e++) { \
        const uint32_t _so = (uint32_t)(((_e * 32 + rb) * GSTRIDE + cl) * 4); \
        cp16(_da + _so, Abase + (size_t)(_e * 32) * K + _ko); \
    } \
    _Pragma("unroll") \
    for (int _e = 0; _e < 4; _e++) { \
        const uint32_t _so = (uint32_t)(((_e * 32 + rb) * GSTRIDE + cl) * 4); \
        cp16(_db + _so, Bbase + (size_t)(_e * 32) * K + _ko); \
    } } while (0)

    LOAD_STAGE64(0, 0); CP_COMMIT();
    if (NC > 1) { LOAD_STAGE64(1, 1); CP_COMMIT(); }

    for (int c = 0; c < NC; c++) {
        if (c + 1 < NC) { CP_WAIT(1); } else { CP_WAIT(0); }
        __syncthreads();
        if (c + 2 < NC) { LOAD_STAGE64(c + 2, (c + 2) % 3); CP_COMMIT(); }

        const uint32_t* Asp = smu + (c % 3) * G64STAGE;
        const uint32_t* Bsp = Asp + 64 * GSTRIDE;

#pragma unroll
        for (int s = 0; s < 4; s++) {
            const int kk = s * 8 + c4;
            uint32_t af[2][4], bf[4][2];
#pragma unroll
            for (int i = 0; i < 2; i++) {
                const int mm = (wm * 32 + i * 16 + g) * GSTRIDE;
                af[i][0] = Asp[mm + kk];
                af[i][1] = Asp[mm + 8 * GSTRIDE + kk];
                af[i][2] = Asp[mm + kk + 4];
                af[i][3] = Asp[mm + 8 * GSTRIDE + kk + 4];
            }
#pragma unroll
            for (int j = 0; j < 4; j++) {
                const int nn = (wn * 32 + j * 8 + g) * GSTRIDE;
                bf[j][0] = Bsp[nn + kk];
                bf[j][1] = Bsp[nn + kk + 4];
            }
#pragma unroll
            for (int i = 0; i < 2; i++)
#pragma unroll
                for (int j = 0; j < 4; j++)
                    mma8(acc[i][j], af[i], bf[j]);
        }
    }
#undef LOAD_STAGE64

#pragma unroll
    for (int i = 0; i < 2; i++) {
        const int r0 = m0 + wm * 32 + i * 16 + g;
        const int r1 = r0 + 8;
#pragma unroll
        for (int j = 0; j < 4; j++) {
            const int col = n0 + wn * 32 + j * 8 + c4 * 2;
            float v0 = acc[i][j][0], v1 = acc[i][j][1];
            float v2 = acc[i][j][2], v3 = acc[i][j][3];
            if (bias) {
                const float b0 = bias[col], b1 = bias[col + 1];
                v0 += b0; v1 += b1; v2 += b0; v3 += b1;
            }
            if (RELU) {
                v0 = fmaxf(v0, 0.f); v1 = fmaxf(v1, 0.f);
                v2 = fmaxf(v2, 0.f); v3 = fmaxf(v3, 0.f);
            }
            if (RESID) {
                const float2 ra = *(const float2*)&R[(size_t)r0 * N + col];
                const float2 rb2 = *(const float2*)&R[(size_t)r1 * N + col];
                v0 += ra.x; v1 += ra.y; v2 += rb2.x; v3 += rb2.y;
            }
            if (CVT) {
                v0 = rnd_tf(v0); v1 = rnd_tf(v1);
                v2 = rnd_tf(v2); v3 = rnd_tf(v3);
            }
            *(float2*)&C[(size_t)r0 * N + col] = make_float2(v0, v1);
            *(float2*)&C[(size_t)r1 * N + col] = make_float2(v2, v3);
        }
    }
}

// ---------------- batched transpose of four 768x768 weights ------------------
struct Ptr4 { const float* p[4]; };
__global__ __launch_bounds__(256) void transpose4_k(Ptr4 ps, float* __restrict__ out)
{
    __shared__ float t[32][33];
    const float* in = ps.p[blockIdx.z];
    float* o = out + (size_t)blockIdx.z * 589824;
    const int n0 = blockIdx.x * 32, k0 = blockIdx.y * 32;
    const int x = threadIdx.x, y = threadIdx.y;
#pragma unroll
    for (int dy = 0; dy < 32; dy += 8)
        t[y + dy][x] = in[(size_t)(k0 + y + dy) * Dn + n0 + x];
    __syncthreads();
#pragma unroll
    for (int dy = 0; dy < 32; dy += 8)
        o[(size_t)(n0 + y + dy) * Dn + k0 + x] = rnd_tf(t[x][y + dy]);
}

// ---------------- generic transpose (+tf32 round) ----------------------------
__global__ __launch_bounds__(256) void transpose_k(
    const float* __restrict__ in, float* __restrict__ out, int Kd, int Nd)
{
    __shared__ float t[32][33];
    const int n0 = blockIdx.x * 32, k0 = blockIdx.y * 32;
    const int x = threadIdx.x, y = threadIdx.y;
#pragma unroll
    for (int dy = 0; dy < 32; dy += 8)
        t[y + dy][x] = in[(size_t)(k0 + y + dy) * Nd + n0 + x];
    __syncthreads();
#pragma unroll
    for (int dy = 0; dy < 32; dy += 8)
        out[(size_t)(n0 + y + dy) * Kd + k0 + x] = rnd_tf(t[x][y + dy]);
}

// ---------------- LayerNorm: float4, 192 threads/row --------------------------
__global__ __launch_bounds__(192) void ln_kernel(
    const float* __restrict__ X, const float* __restrict__ g,
    const float* __restrict__ b, float* __restrict__ Y)
{
    const int row = blockIdx.x;
    const int tid = threadIdx.x;
    const float4 v = *(const float4*)&X[(size_t)row * Dn + tid * 4];
    float s  = v.x + v.y + v.z + v.w;
    float s2 = v.x * v.x + v.y * v.y + v.z * v.z + v.w * v.w;
#pragma unroll
    for (int o = 16; o > 0; o >>= 1) {
        s  += __shfl_down_sync(0xffffffffu, s,  o);
        s2 += __shfl_down_sync(0xffffffffu, s2, o);
    }
    __shared__ float rs[6], rs2[6];
    __shared__ float sh_mean, sh_inv;
    const int w = tid >> 5, ln = tid & 31;
    if (ln == 0) { rs[w] = s; rs2[w] = s2; }
    __syncthreads();
    if (tid == 0) {
        float a = 0.f, a2 = 0.f;
#pragma unroll
        for (int i = 0; i < 6; i++) { a += rs[i]; a2 += rs2[i]; }
        float m = a * (1.f / Dn);
        float var = a2 * (1.f / Dn) - m * m;
        sh_mean = m;
        sh_inv = rsqrtf(var + 1e-5f);
    }
    __syncthreads();
    const float m = sh_mean, inv = sh_inv;
    const float4 gg = *(const float4*)&g[tid * 4];
    const float4 bb = *(const float4*)&b[tid * 4];
    float4 o;
    o.x = rnd_tf((v.x - m) * inv * gg.x + bb.x);
    o.y = rnd_tf((v.y - m) * inv * gg.y + bb.y);
    o.z = rnd_tf((v.z - m) * inv * gg.z + bb.z);
    o.w = rnd_tf((v.w - m) * inv * gg.w + bb.w);
    *(float4*)&Y[(size_t)row * Dn + tid * 4] = o;
}

// ============ Tensor-core flash attention (tf32 mma, double-buffered KV) ====
#define APAD 68
#define VPAD 72
#define ATT_SMEM ((128*APAD + 2*64*APAD + 2*64*VPAD) * 4 + 2*64*4)

__global__ void __launch_bounds__(256, 2) attn_mma_kernel(
    const float* __restrict__ QKV, const int* __restrict__ msk,
    float* __restrict__ O)
{
    extern __shared__ __align__(16) float sm[];
    float* Ps  = sm;                          // [128][APAD] (Q staging, then P)
    float* Ks0 = sm + 128 * APAD;             // 2 stages of [64][APAD]
    float* Vs0 = Ks0 + 2 * 64 * APAD;         // 2 stages of [64][VPAD]
    int*   ms0 = (int*)(Vs0 + 2 * 64 * VPAD); // 2 stages of [64]
    uint32_t* Pu = (uint32_t*)Ps;
    const uint32_t sb   = smem_to_u32(sm);
    const uint32_t kbs0 = sb + 128 * APAD * 4;
    const uint32_t vbs0 = kbs0 + 2 * 64 * APAD * 4;
    const uint32_t mbs0 = vbs0 + 2 * 64 * VPAD * 4;

    const int qt = blockIdx.x, h = blockIdx.y, b = blockIdx.z;
    const int tid = threadIdx.x;
    const int w = tid >> 5, lane = tid & 31;
    const int g = lane >> 2, c4 = lane & 3;
    const size_t base  = (size_t)b * Tn * QKVs + (size_t)h * HSn;
    const size_t obase = (size_t)b * Tn * Dn + (size_t)h * HSn;
    const int q0 = qt * 128;

#define LOAD_KV(kt_, st_) do { \
    const uint32_t _kb = kbs0 + (uint32_t)(st_) * 64 * APAD * 4; \
    const uint32_t _vb = vbs0 + (uint32_t)(st_) * 64 * VPAD * 4; \
    _Pragma("unroll") \
    for (int _e = 0; _e < 4; _e++) { \
        int _idx = tid + _e * 256; \
        int _r = _idx >> 4, _cc = (_idx & 15) * 4; \
        size_t _gi = base + (size_t)((kt_) + _r) * QKVs + _cc; \
        cp16(_kb + (uint32_t)(_r * APAD + _cc) * 4, &QKV[_gi + 768]); \
        cp16(_vb + (uint32_t)(_r * VPAD + _cc) * 4, &QKV[_gi + 1536]); \
    } \
    if (tid < 16) cp16(mbs0 + (uint32_t)(st_) * 256 + tid * 16, \
                       (const float*)(msk + b * Tn + (kt_) + tid * 4)); \
    } while (0)

    // stage Q
#pragma unroll
    for (int e = 0; e < 8; e++) {
        int idx = tid + e * 256;
        int r = idx >> 4, cc = (idx & 15) * 4;
        cp16(sb + (uint32_t)(r * APAD + cc) * 4,
             &QKV[base + (size_t)(q0 + r) * QKVs + cc]);
    }
    CP_COMMIT();
    LOAD_KV(0, 0); CP_COMMIT();
    CP_WAIT(1);                // Q complete (KV0 may still be in flight)
    __syncthreads();

    uint32_t qf[8][4];
#pragma unroll
    for (int kc = 0; kc < 8; kc++) {
        int r0 = (w * 16 + g) * APAD + kc * 8 + c4;
        qf[kc][0] = Pu[r0];
        qf[kc][1] = Pu[r0 + 8 * APAD];
        qf[kc][2] = Pu[r0 + 4];
        qf[kc][3] = Pu[r0 + 8 * APAD + 4];
    }
    __syncthreads();

    float m0r = -1e30f, m1r = -1e30f, l0 = 0.f, l1 = 0.f;
    float o[8][4];
#pragma unroll
    for (int nt = 0; nt < 8; nt++)
#pragma unroll
        for (int e = 0; e < 4; e++) o[nt][e] = 0.f;

    const float rsc = 0.03608439182435161f;  // 768^-0.5 (embed_dim, not hs)

    for (int t = 0; t < Tn / 64; t++) {
        if (t + 1 < Tn / 64) {
            LOAD_KV((t + 1) * 64, (t + 1) & 1); CP_COMMIT();
            CP_WAIT(1);
        } else {
            CP_WAIT(0);
        }
        __syncthreads();

        const uint32_t* Ku = (const uint32_t*)(Ks0 + (t & 1) * 64 * APAD);
        const uint32_t* Vu = (const uint32_t*)(Vs0 + (t & 1) * 64 * VPAD);
        const int* msp = ms0 + (t & 1) * 64;

        float s[8][4];
#pragma unroll
        for (int nt = 0; nt < 8; nt++)
#pragma unroll
            for (int e = 0; e < 4; e++) s[nt][e] = 0.f;
#pragma unroll
        for (int kc = 0; kc < 8; kc++) {
#pragma unroll
            for (int nt = 0; nt < 8; nt++) {
                uint32_t bf[2];
                int ka = (nt * 8 + g) * APAD + kc * 8 + c4;
                bf[0] = Ku[ka];
                bf[1] = Ku[ka + 4];
                mma8(s[nt], qf[kc], bf);
            }
        }

        float mx0 = -1e30f, mx1 = -1e30f;
#pragma unroll
        for (int nt = 0; nt < 8; nt++) {
            const int mk0 = msp[nt * 8 + 2 * c4], mk1 = msp[nt * 8 + 2 * c4 + 1];
            s[nt][0] = mk0 ? s[nt][0] * rsc : -1e30f;
            s[nt][1] = mk1 ? s[nt][1] * rsc : -1e30f;
            s[nt][2] = mk0 ? s[nt][2] * rsc : -1e30f;
            s[nt][3] = mk1 ? s[nt][3] * rsc : -1e30f;
            mx0 = fmaxf(mx0, fmaxf(s[nt][0], s[nt][1]));
            mx1 = fmaxf(mx1, fmaxf(s[nt][2], s[nt][3]));
        }
        mx0 = fmaxf(mx0, __shfl_xor_sync(0xffffffffu, mx0, 1));
        mx0 = fmaxf(mx0, __shfl_xor_sync(0xffffffffu, mx0, 2));
        mx1 = fmaxf(mx1, __shfl_xor_sync(0xffffffffu, mx1, 1));
        mx1 = fmaxf(mx1, __shfl_xor_sync(0xffffffffu, mx1, 2));

        const float mn0 = fmaxf(m0r, mx0), mn1 = fmaxf(m1r, mx1);
        const float a0 = __expf(m0r - mn0), a1 = __expf(m1r - mn1);
        float rs0 = 0.f, rs1 = 0.f;
#pragma unroll
        for (int nt = 0; nt < 8; nt++) {
            float p0 = __expf(s[nt][0] - mn0);
            float p1 = __expf(s[nt][1] - mn0);
            float p2 = __expf(s[nt][2] - mn1);
            float p3 = __expf(s[nt][3] - mn1);
            rs0 += p0 + p1;
            rs1 += p2 + p3;
            int pa = (w * 16 + g) * APAD + nt * 8 + 2 * c4;
            Pu[pa]                = __float_as_uint(p0);
            Pu[pa + 1]            = __float_as_uint(p1);
            Pu[pa + 8 * APAD]     = __float_as_uint(p2);
            Pu[pa + 8 * APAD + 1] = __float_as_uint(p3);
        }
        rs0 += __shfl_xor_sync(0xffffffffu, rs0, 1);
        rs0 += __shfl_xor_sync(0xffffffffu, rs0, 2);
        rs1 += __shfl_xor_sync(0xffffffffu, rs1, 1);
        rs1 += __shfl_xor_sync(0xffffffffu, rs1, 2);
        l0 = l0 * a0 + rs0;
        l1 = l1 * a1 + rs1;
        m0r = mn0; m1r = mn1;
#pragma unroll
        for (int nt = 0; nt < 8; nt++) {
            o[nt][0] *= a0; o[nt][1] *= a0;
            o[nt][2] *= a1; o[nt][3] *= a1;
        }
        __syncwarp();

#pragma unroll
        for (int kc = 0; kc < 8; kc++) {
            uint32_t pf[4];
            int pa = (w * 16 + g) * APAD + kc * 8 + c4;
            pf[0] = Pu[pa];
            pf[1] = Pu[pa + 8 * APAD];
            pf[2] = Pu[pa + 4];
            pf[3] = Pu[pa + 8 * APAD + 4];
#pragma unroll
            for (int nt = 0; nt < 8; nt++) {
                uint32_t bf[2];
                int va = (kc * 8 + c4) * VPAD + nt * 8 + g;
                bf[0] = Vu[va];
                bf[1] = Vu[va + 4 * VPAD];
                mma8(o[nt], pf, bf);
            }
        }
        __syncthreads();
    }
#undef LOAD_KV

    const float il0 = 1.f / l0, il1 = 1.f / l1;
    const int r0 = q0 + w * 16 + g;
#pragma unroll
    for (int nt = 0; nt < 8; nt++) {
        const int col = nt * 8 + 2 * c4;
        *(float2*)&O[obase + (size_t)r0 * Dn + col] =
            make_float2(rnd_tf(o[nt][0] * il0), rnd_tf(o[nt][1] * il0));
        *(float2*)&O[obase + (size_t)(r0 + 8) * Dn + col] =
            make_float2(rnd_tf(o[nt][2] * il1), rnd_tf(o[nt][3] * il1));
    }
}

// ---------------- launch ----------------------------------------------------
extern "C" void kernel_launch(void* const* d_in, const int* in_sizes, int n_in,
                              void* d_out, int out_size)
{
    (void)in_sizes; (void)n_in; (void)out_size;
    const float* x    = (const float*)d_in[0];
    const int*   mask = (const int*)d_in[1];
    const float* Wq   = (const float*)d_in[2];
    const float* Wk   = (const float*)d_in[3];
    const float* Wv   = (const float*)d_in[4];
    const float* Wo   = (const float*)d_in[5];
    const float* bo   = (const float*)d_in[6];
    const float* l1g  = (const float*)d_in[7];
    const float* l1b  = (const float*)d_in[8];
    const float* l2g  = (const float*)d_in[9];
    const float* l2b  = (const float*)d_in[10];
    const float* W1   = (const float*)d_in[11];
    const float* b1   = (const float*)d_in[12];
    const float* W2   = (const float*)d_in[13];
    const float* b2   = (const float*)d_in[14];
    float* out = (float*)d_out;

    float *ph, *pqkv, *pa, *pf, *pw;
    cudaGetSymbolAddress((void**)&ph, g_h);
    cudaGetSymbolAddress((void**)&pqkv, g_qkv);
    cudaGetSymbolAddress((void**)&pa, g_att);
    cudaGetSymbolAddress((void**)&pf, g_ff);
    cudaGetSymbolAddress((void**)&pw, g_wt);

    float* wqkvT = pw;                       // wq|wk|wv stacked, then wo
    float* woT   = pw + 3 * 589824;
    float* w1T   = pw + 4 * 589824;
    float* w2T   = pw + 4 * 589824 + 2359296;

    cudaFuncSetAttribute(attn_mma_kernel,
                         cudaFuncAttributeMaxDynamicSharedMemorySize, ATT_SMEM);
    cudaFuncSetAttribute(mgemm_k<false, false, true>,
                         cudaFuncAttributeMaxDynamicSharedMemorySize, GEMM_SMEM);
    cudaFuncSetAttribute(mgemm_k<true, false, true>,
                         cudaFuncAttributeMaxDynamicSharedMemorySize, GEMM_SMEM);
    cudaFuncSetAttribute(mgemm64_k<false, true, false>,
                         cudaFuncAttributeMaxDynamicSharedMemorySize, GEMM64_SMEM);

    // 0) transpose weights to [N,K] K-major, rounded to tf32 grid
    dim3 tb(32, 8);
    Ptr4 p4; p4.p[0] = Wq; p4.p[1] = Wk; p4.p[2] = Wv; p4.p[3] = Wo;
    transpose4_k<<<dim3(Dn / 32, Dn / 32, 4), tb>>>(p4, wqkvT);
    transpose_k<<<dim3(DFFn / 32, Dn / 32), tb>>>(W1, w1T, Dn, DFFn);
    transpose_k<<<dim3(Dn / 32, DFFn / 32), tb>>>(W2, w2T, DFFn, Dn);

    // 1) h = ln1(x)
    ln_kernel<<<BTn, 192>>>(x, l1g, l1b, ph);

    // 2) qkv = h @ [Wq|Wk|Wv]
    mgemm_k<false, false, true><<<dim3(QKVs / 128, BTn / 128), 256, GEMM_SMEM>>>(
        ph, wqkvT, nullptr, nullptr, pqkv, BTn, QKVs, Dn);

    // 3) tensor-core flash attention (double-buffered KV)
    attn_mma_kernel<<<dim3(Tn / 128, Hn, Bq), 256, ATT_SMEM>>>(pqkv, mask, pa);

    // 4) x2 = x + att @ Wo + bo  -> d_out
    mgemm64_k<false, true, false><<<dim3(Dn / 128, BTn / 64), 256, GEMM64_SMEM>>>(
        pa, woT, bo, x, out, BTn, Dn, Dn);

    // 5) h2 = ln2(x2)
    ln_kernel<<<BTn, 192>>>(out, l2g, l2b, ph);

    // 6) ff = relu(h2 @ W1 + b1)
    mgemm_k<true, false, true><<<dim3(DFFn / 128, BTn / 128), 256, GEMM_SMEM>>>(
        ph, w1T, b1, nullptr, pf, BTn, DFFn, Dn);

    // 7) out = x2 + ff @ W2 + b2
    mgemm64_k<false, true, false><<<dim3(Dn / 128, BTn / 64), 256, GEMM64_SMEM>>>(
        pf, w2T, b2, out, out, BTn, Dn, DFFn);
}

// round 8
// speedup vs baseline: 7.2987x; 1.7933x over previous
#include <cuda_runtime.h>
#include <cuda_fp16.h>
#include <cstdint>

#define Bq 2
#define Tn 2048
#define Dn 768
#define Hn 12
#define HSn 64
#define BTn (Bq*Tn)
#define DFFn (4*Dn)
#define QKVs 2304

// ---------------- scratch (static device globals; no allocations) -----------
__device__ __half g_h[(size_t)BTn*Dn];       // ln1(x) / ln2(x2), fp16
__device__ __half g_qkv[(size_t)BTn*QKVs];   // [q|k|v] per row, fp16
__device__ __half g_att[(size_t)BTn*Dn];     // attention output, fp16
__device__ __half g_ff[(size_t)BTn*DFFn];    // relu(h2 W1 + b1), fp16
__device__ __half g_wt[4*589824 + 2*2359296];// transposed weights, fp16

// ---------------- helpers ----------------------------------------------------
__device__ __forceinline__ uint32_t smem_to_u32(const void* p) {
    uint32_t a;
    asm("{ .reg .u64 t; cvta.to.shared.u64 t, %1; cvt.u32.u64 %0, t; }"
        : "=r"(a) : "l"(p));
    return a;
}
__device__ __forceinline__ void cp16(uint32_t s, const void* g) {
    asm volatile("cp.async.cg.shared.global [%0], [%1], 16;" :: "r"(s), "l"(g));
}
#define CP_COMMIT() asm volatile("cp.async.commit_group;" ::: "memory")
#define CP_WAIT(n)  asm volatile("cp.async.wait_group %0;" :: "n"(n) : "memory")

// pack two floats -> half2 bits (lo = a, hi = b)
__device__ __forceinline__ uint32_t h2bits(float a, float b) {
    uint32_t r;
    asm("cvt.rn.f16x2.f32 %0, %1, %2;" : "=r"(r) : "f"(b), "f"(a));
    return r;
}
// fp16 mma m16n8k16, f32 accumulate
__device__ __forceinline__ void mma16(float* d, const uint32_t* a,
                                      uint32_t b0, uint32_t b1) {
    asm volatile(
        "mma.sync.aligned.m16n8k16.row.col.f32.f16.f16.f32 "
        "{%0,%1,%2,%3}, {%4,%5,%6,%7}, {%8,%9}, {%0,%1,%2,%3};"
        : "+f"(d[0]), "+f"(d[1]), "+f"(d[2]), "+f"(d[3])
        : "r"(a[0]), "r"(a[1]), "r"(a[2]), "r"(a[3]), "r"(b0), "r"(b1));
}
__device__ __forceinline__ void ldsm4t(uint32_t& r0, uint32_t& r1,
                                       uint32_t& r2, uint32_t& r3, uint32_t a) {
    asm volatile(
        "ldmatrix.sync.aligned.m8n8.x4.trans.shared.b16 {%0,%1,%2,%3}, [%4];"
        : "=r"(r0), "=r"(r1), "=r"(r2), "=r"(r3) : "r"(a));
}

// ============== fp16 mma GEMM (128x128 tile): C = A[M,K] * BT[N,K]^T =========
// BK=64 halves, 256 threads (8 warps 2x4), warp tile 64x32, 3-stage cp.async.
// smem rows of 72 halves (36 u32, pad) -> bank 4g+c4, conflict-free.
#define GSTRIDE 36                         // u32 per smem row
#define GSTAGE  (128*GSTRIDE)              // u32 per matrix per stage
#define GEMM_SMEM (3*2*GSTAGE*4)           // 110592 bytes

template<bool RELU, bool RESID, bool HOUT>
__global__ void __launch_bounds__(256, 2) mgemm_k(
    const __half* __restrict__ A, const __half* __restrict__ BT,
    const float* __restrict__ bias, const float* __restrict__ R,
    void* __restrict__ Cv, int M, int N, int K)
{
    extern __shared__ __align__(16) uint32_t smu[];
    const uint32_t sb = smem_to_u32(smu);

    const int tid = threadIdx.x;
    const int wid = tid >> 5, lane = tid & 31;
    const int g = lane >> 2, c4 = lane & 3;
    const int wm = wid & 1, wn = wid >> 1;
    const int m0 = blockIdx.y * 128, n0 = blockIdx.x * 128;

    float acc[4][4][4];
#pragma unroll
    for (int i = 0; i < 4; i++)
#pragma unroll
        for (int j = 0; j < 4; j++)
#pragma unroll
            for (int e = 0; e < 4; e++) acc[i][j][e] = 0.f;

    const int NC = K >> 6;                 // 64 halves per chunk

#define LOAD_STAGE(c_, s_) do { \
    const uint32_t _da = sb + (uint32_t)((s_) * 2 * GSTAGE) * 4u; \
    const uint32_t _db = _da + GSTAGE * 4u; \
    const int _ko = (c_) * 64; \
    _Pragma("unroll") \
    for (int _e = 0; _e < 4; _e++) { \
        const int _idx = tid + _e * 256; \
        const int _r = _idx >> 3, _cg = (_idx & 7) * 8; \
        const uint32_t _so = (uint32_t)(_r * 72 + _cg) * 2u; \
        cp16(_da + _so, A  + (size_t)(m0 + _r) * K + _ko + _cg); \
        cp16(_db + _so, BT + (size_t)(n0 + _r) * K + _ko + _cg); \
    } } while (0)

    LOAD_STAGE(0, 0); CP_COMMIT();
    if (NC > 1) { LOAD_STAGE(1, 1); CP_COMMIT(); }

    for (int c = 0; c < NC; c++) {
        if (c + 1 < NC) { CP_WAIT(1); } else { CP_WAIT(0); }
        __syncthreads();
        if (c + 2 < NC) { LOAD_STAGE(c + 2, (c + 2) % 3); CP_COMMIT(); }

        const uint32_t* Asp = smu + (c % 3) * 2 * GSTAGE;
        const uint32_t* Bsp = Asp + GSTAGE;

#pragma unroll
        for (int s = 0; s < 4; s++) {       // 4 k16 steps
            const int kk = s * 8 + c4;
            uint32_t af[4][4], bf[4][2];
#pragma unroll
            for (int i = 0; i < 4; i++) {
                const int mm = (wm * 64 + i * 16 + g) * GSTRIDE;
                af[i][0] = Asp[mm + kk];
                af[i][1] = Asp[mm + 8 * GSTRIDE + kk];
                af[i][2] = Asp[mm + kk + 4];
                af[i][3] = Asp[mm + 8 * GSTRIDE + kk + 4];
            }
#pragma unroll
            for (int j = 0; j < 4; j++) {
                const int nn = (wn * 32 + j * 8 + g) * GSTRIDE;
                bf[j][0] = Bsp[nn + kk];
                bf[j][1] = Bsp[nn + kk + 4];
            }
#pragma unroll
            for (int i = 0; i < 4; i++)
#pragma unroll
                for (int j = 0; j < 4; j++)
                    mma16(acc[i][j], af[i], bf[j][0], bf[j][1]);
        }
    }
#undef LOAD_STAGE

#pragma unroll
    for (int i = 0; i < 4; i++) {
        const int r0 = m0 + wm * 64 + i * 16 + g;
        const int r1 = r0 + 8;
#pragma unroll
        for (int j = 0; j < 4; j++) {
            const int col = n0 + wn * 32 + j * 8 + c4 * 2;
            float v0 = acc[i][j][0], v1 = acc[i][j][1];
            float v2 = acc[i][j][2], v3 = acc[i][j][3];
            if (bias) {
                const float b0 = bias[col], b1 = bias[col + 1];
                v0 += b0; v1 += b1; v2 += b0; v3 += b1;
            }
            if (RELU) {
                v0 = fmaxf(v0, 0.f); v1 = fmaxf(v1, 0.f);
                v2 = fmaxf(v2, 0.f); v3 = fmaxf(v3, 0.f);
            }
            if (RESID) {
                const float2 ra = *(const float2*)&R[(size_t)r0 * N + col];
                const float2 rb = *(const float2*)&R[(size_t)r1 * N + col];
                v0 += ra.x; v1 += ra.y; v2 += rb.x; v3 += rb.y;
            }
            if (HOUT) {
                __half* C = (__half*)Cv;
                *(uint32_t*)&C[(size_t)r0 * N + col] = h2bits(v0, v1);
                *(uint32_t*)&C[(size_t)r1 * N + col] = h2bits(v2, v3);
            } else {
                float* C = (float*)Cv;
                *(float2*)&C[(size_t)r0 * N + col] = make_float2(v0, v1);
                *(float2*)&C[(size_t)r1 * N + col] = make_float2(v2, v3);
            }
        }
    }
}

// ============== fp16 mma GEMM (64x128 tile) — Wo / W2 (f32+resid out) =======
#define G64STAGE ((64+128)*GSTRIDE)
#define GEMM64_SMEM (3*G64STAGE*4)         // 82944 bytes

template<bool RELU, bool RESID>
__global__ void __launch_bounds__(256, 2) mgemm64_k(
    const __half* __restrict__ A, const __half* __restrict__ BT,
    const float* __restrict__ bias, const float* __restrict__ R,
    float* __restrict__ C, int M, int N, int K)
{
    extern __shared__ __align__(16) uint32_t smu[];
    const uint32_t sb = smem_to_u32(smu);

    const int tid = threadIdx.x;
    const int wid = tid >> 5, lane = tid & 31;
    const int g = lane >> 2, c4 = lane & 3;
    const int wm = wid & 1, wn = wid >> 1;
    const int m0 = blockIdx.y * 64, n0 = blockIdx.x * 128;

    float acc[2][4][4];
#pragma unroll
    for (int i = 0; i < 2; i++)
#pragma unroll
        for (int j = 0; j < 4; j++)
#pragma unroll
            for (int e = 0; e < 4; e++) acc[i][j][e] = 0.f;

    const int NC = K >> 6;

#define LOAD_STAGE64(c_, s_) do { \
    const uint32_t _da = sb + (uint32_t)((s_) * G64STAGE) * 4u; \
    const uint32_t _db = _da + 64u * GSTRIDE * 4u; \
    const int _ko = (c_) * 64; \
    _Pragma("unroll") \
    for (int _e = 0; _e < 2; _e++) { \
        const int _idx = tid + _e * 256; \
        const int _r = _idx >> 3, _cg = (_idx & 7) * 8; \
        cp16(_da + (uint32_t)(_r * 72 + _cg) * 2u, \
             A + (size_t)(m0 + _r) * K + _ko + _cg); \
    } \
    _Pragma("unroll") \
    for (int _e = 0; _e < 4; _e++) { \
        const int _idx = tid + _e * 256; \
        const int _r = _idx >> 3, _cg = (_idx & 7) * 8; \
        cp16(_db + (uint32_t)(_r * 72 + _cg) * 2u, \
             BT + (size_t)(n0 + _r) * K + _ko + _cg); \
    } } while (0)

    LOAD_STAGE64(0, 0); CP_COMMIT();
    if (NC > 1) { LOAD_STAGE64(1, 1); CP_COMMIT(); }

    for (int c = 0; c < NC; c++) {
        if (c + 1 < NC) { CP_WAIT(1); } else { CP_WAIT(0); }
        __syncthreads();
        if (c + 2 < NC) { LOAD_STAGE64(c + 2, (c + 2) % 3); CP_COMMIT(); }

        const uint32_t* Asp = smu + (c % 3) * G64STAGE;
        const uint32_t* Bsp = Asp + 64 * GSTRIDE;

#pragma unroll
        for (int s = 0; s < 4; s++) {
            const int kk = s * 8 + c4;
            uint32_t af[2][4], bf[4][2];
#pragma unroll
            for (int i = 0; i < 2; i++) {
                const int mm = (wm * 32 + i * 16 + g) * GSTRIDE;
                af[i][0] = Asp[mm + kk];
                af[i][1] = Asp[mm + 8 * GSTRIDE + kk];
                af[i][2] = Asp[mm + kk + 4];
                af[i][3] = Asp[mm + 8 * GSTRIDE + kk + 4];
            }
#pragma unroll
            for (int j = 0; j < 4; j++) {
                const int nn = (wn * 32 + j * 8 + g) * GSTRIDE;
                bf[j][0] = Bsp[nn + kk];
                bf[j][1] = Bsp[nn + kk + 4];
            }
#pragma unroll
            for (int i = 0; i < 2; i++)
#pragma unroll
                for (int j = 0; j < 4; j++)
                    mma16(acc[i][j], af[i], bf[j][0], bf[j][1]);
        }
    }
#undef LOAD_STAGE64

#pragma unroll
    for (int i = 0; i < 2; i++) {
        const int r0 = m0 + wm * 32 + i * 16 + g;
        const int r1 = r0 + 8;
#pragma unroll
        for (int j = 0; j < 4; j++) {
            const int col = n0 + wn * 32 + j * 8 + c4 * 2;
            float v0 = acc[i][j][0], v1 = acc[i][j][1];
            float v2 = acc[i][j][2], v3 = acc[i][j][3];
            if (bias) {
                const float b0 = bias[col], b1 = bias[col + 1];
                v0 += b0; v1 += b1; v2 += b0; v3 += b1;
            }
            if (RELU) {
                v0 = fmaxf(v0, 0.f); v1 = fmaxf(v1, 0.f);
                v2 = fmaxf(v2, 0.f); v3 = fmaxf(v3, 0.f);
            }
            if (RESID) {
                const float2 ra = *(const float2*)&R[(size_t)r0 * N + col];
                const float2 rb = *(const float2*)&R[(size_t)r1 * N + col];
                v0 += ra.x; v1 += ra.y; v2 += rb.x; v3 += rb.y;
            }
            *(float2*)&C[(size_t)r0 * N + col] = make_float2(v0, v1);
            *(float2*)&C[(size_t)r1 * N + col] = make_float2(v2, v3);
        }
    }
}

// ---------------- batched transpose of four 768x768 weights (f32 -> f16) ----
struct Ptr4 { const float* p[4]; };
__global__ __launch_bounds__(256) void transpose4_k(Ptr4 ps, __half* __restrict__ out)
{
    __shared__ float t[32][33];
    const float* in = ps.p[blockIdx.z];
    __half* o = out + (size_t)blockIdx.z * 589824;
    const int n0 = blockIdx.x * 32, k0 = blockIdx.y * 32;
    const int x = threadIdx.x, y = threadIdx.y;
#pragma unroll
    for (int dy = 0; dy < 32; dy += 8)
        t[y + dy][x] = in[(size_t)(k0 + y + dy) * Dn + n0 + x];
    __syncthreads();
#pragma unroll
    for (int dy = 0; dy < 32; dy += 8)
        o[(size_t)(n0 + y + dy) * Dn + k0 + x] = __float2half_rn(t[x][y + dy]);
}

__global__ __launch_bounds__(256) void transpose_k(
    const float* __restrict__ in, __half* __restrict__ out, int Kd, int Nd)
{
    __shared__ float t[32][33];
    const int n0 = blockIdx.x * 32, k0 = blockIdx.y * 32;
    const int x = threadIdx.x, y = threadIdx.y;
#pragma unroll
    for (int dy = 0; dy < 32; dy += 8)
        t[y + dy][x] = in[(size_t)(k0 + y + dy) * Nd + n0 + x];
    __syncthreads();
#pragma unroll
    for (int dy = 0; dy < 32; dy += 8)
        out[(size_t)(n0 + y + dy) * Kd + k0 + x] = __float2half_rn(t[x][y + dy]);
}

// ---------------- LayerNorm: f32 in, f16 out, 192 threads/row ----------------
__global__ __launch_bounds__(192) void ln_kernel(
    const float* __restrict__ X, const float* __restrict__ g,
    const float* __restrict__ b, __half* __restrict__ Y)
{
    const int row = blockIdx.x;
    const int tid = threadIdx.x;
    const float4 v = *(const float4*)&X[(size_t)row * Dn + tid * 4];
    float s  = v.x + v.y + v.z + v.w;
    float s2 = v.x * v.x + v.y * v.y + v.z * v.z + v.w * v.w;
#pragma unroll
    for (int o = 16; o > 0; o >>= 1) {
        s  += __shfl_down_sync(0xffffffffu, s,  o);
        s2 += __shfl_down_sync(0xffffffffu, s2, o);
    }
    __shared__ float rs[6], rs2[6];
    __shared__ float sh_mean, sh_inv;
    const int w = tid >> 5, ln = tid & 31;
    if (ln == 0) { rs[w] = s; rs2[w] = s2; }
    __syncthreads();
    if (tid == 0) {
        float a = 0.f, a2 = 0.f;
#pragma unroll
        for (int i = 0; i < 6; i++) { a += rs[i]; a2 += rs2[i]; }
        float m = a * (1.f / Dn);
        float var = a2 * (1.f / Dn) - m * m;
        sh_mean = m;
        sh_inv = rsqrtf(var + 1e-5f);
    }
    __syncthreads();
    const float m = sh_mean, inv = sh_inv;
    const float4 gg = *(const float4*)&g[tid * 4];
    const float4 bb = *(const float4*)&b[tid * 4];
    uint2 u;
    u.x = h2bits((v.x - m) * inv * gg.x + bb.x, (v.y - m) * inv * gg.y + bb.y);
    u.y = h2bits((v.z - m) * inv * gg.z + bb.z, (v.w - m) * inv * gg.w + bb.w);
    *(uint2*)&Y[(size_t)row * Dn + tid * 4] = u;
}

// ============ fp16 tensor-core flash attention (double-buffered KV) =========
// smem (halves, 72/row): Q/P 128x72, K 2x64x72, V 2x64x72, masks 2x64 ints.
#define ASTR 72
#define ATT_SMEM (128*ASTR*2 + 2*64*ASTR*2 + 2*64*ASTR*2 + 2*64*4)

__global__ void __launch_bounds__(256, 2) attn_mma_kernel(
    const __half* __restrict__ QKV, const int* __restrict__ msk,
    __half* __restrict__ O)
{
    extern __shared__ __align__(16) __half sm[];
    uint32_t* Pu = (uint32_t*)sm;                 // Q staging, then P
    const uint32_t sb   = smem_to_u32(sm);
    const uint32_t kbs0 = sb + 128 * ASTR * 2;
    const uint32_t vbs0 = kbs0 + 2 * 64 * ASTR * 2;
    const uint32_t mbs0 = vbs0 + 2 * 64 * ASTR * 2;
    __half* Ks0 = sm + 128 * ASTR;
    int*    ms0 = (int*)(sm + 128 * ASTR + 4 * 64 * ASTR);

    const int qt = blockIdx.x, h = blockIdx.y, b = blockIdx.z;
    const int tid = threadIdx.x;
    const int w = tid >> 5, lane = tid & 31;
    const int g = lane >> 2, c4 = lane & 3;
    const size_t base  = (size_t)b * Tn * QKVs + (size_t)h * HSn;
    const size_t obase = (size_t)b * Tn * Dn + (size_t)h * HSn;
    const int q0 = qt * 128;

#define LOAD_KV(kt_, st_) do { \
    const uint32_t _kb = kbs0 + (uint32_t)(st_) * 64 * ASTR * 2; \
    const uint32_t _vb = vbs0 + (uint32_t)(st_) * 64 * ASTR * 2; \
    _Pragma("unroll") \
    for (int _e = 0; _e < 2; _e++) { \
        const int _idx = tid + _e * 256; \
        const int _r = _idx >> 3, _cg = (_idx & 7) * 8; \
        const size_t _gi = base + (size_t)((kt_) + _r) * QKVs + _cg; \
        const uint32_t _so = (uint32_t)(_r * ASTR + _cg) * 2u; \
        cp16(_kb + _so, QKV + _gi + 768); \
        cp16(_vb + _so, QKV + _gi + 1536); \
    } \
    if (tid < 16) cp16(mbs0 + (uint32_t)(st_) * 256 + tid * 16, \
                       msk + b * Tn + (kt_) + tid * 4); \
    } while (0)

    // stage Q (fp16, cp.async)
#pragma unroll
    for (int e = 0; e < 4; e++) {
        const int idx = tid + e * 256;
        const int r = idx >> 3, cg = (idx & 7) * 8;
        cp16(sb + (uint32_t)(r * ASTR + cg) * 2u,
             QKV + base + (size_t)(q0 + r) * QKVs + cg);
    }
    CP_COMMIT();
    LOAD_KV(0, 0); CP_COMMIT();
    CP_WAIT(1);
    __syncthreads();

    // Q fragments -> registers (4 k16 steps)
    uint32_t qf[4][4];
#pragma unroll
    for (int kc = 0; kc < 4; kc++) {
        const int i0 = (w * 16 + g) * (ASTR / 2) + kc * 8 + c4;
        qf[kc][0] = Pu[i0];
        qf[kc][1] = Pu[i0 + 8 * (ASTR / 2)];
        qf[kc][2] = Pu[i0 + 4];
        qf[kc][3] = Pu[i0 + 8 * (ASTR / 2) + 4];
    }
    __syncthreads();   // Q buffer now free for P

    float m0r = -1e30f, m1r = -1e30f, l0 = 0.f, l1 = 0.f;
    float o[8][4];
#pragma unroll
    for (int nt = 0; nt < 8; nt++)
#pragma unroll
        for (int e = 0; e < 4; e++) o[nt][e] = 0.f;

    const float rsc = 0.03608439182435161f;  // 768^-0.5 (embed_dim, not hs)

    for (int t = 0; t < Tn / 64; t++) {
        if (t + 1 < Tn / 64) {
            LOAD_KV((t + 1) * 64, (t + 1) & 1); CP_COMMIT();
            CP_WAIT(1);
        } else {
            CP_WAIT(0);
        }
        __syncthreads();

        const uint32_t* Ku = (const uint32_t*)(Ks0 + (t & 1) * 64 * ASTR);
        const uint32_t  vst = vbs0 + (uint32_t)(t & 1) * 64 * ASTR * 2;
        const int* msp = ms0 + (t & 1) * 64;

        // S = Q K^T (32 fp16 MMAs)
        float s[8][4];
#pragma unroll
        for (int nt = 0; nt < 8; nt++)
#pragma unroll
            for (int e = 0; e < 4; e++) s[nt][e] = 0.f;
#pragma unroll
        for (int kc = 0; kc < 4; kc++) {
#pragma unroll
            for (int nt = 0; nt < 8; nt++) {
                const int ka = (nt * 8 + g) * (ASTR / 2) + kc * 8 + c4;
                mma16(s[nt], qf[kc], Ku[ka], Ku[ka + 4]);
            }
        }

        // mask + scale + online softmax
        float mx0 = -1e30f, mx1 = -1e30f;
#pragma unroll
        for (int nt = 0; nt < 8; nt++) {
            const int mk0 = msp[nt * 8 + 2 * c4], mk1 = msp[nt * 8 + 2 * c4 + 1];
            s[nt][0] = mk0 ? s[nt][0] * rsc : -1e30f;
            s[nt][1] = mk1 ? s[nt][1] * rsc : -1e30f;
            s[nt][2] = mk0 ? s[nt][2] * rsc : -1e30f;
            s[nt][3] = mk1 ? s[nt][3] * rsc : -1e30f;
            mx0 = fmaxf(mx0, fmaxf(s[nt][0], s[nt][1]));
            mx1 = fmaxf(mx1, fmaxf(s[nt][2], s[nt][3]));
        }
        mx0 = fmaxf(mx0, __shfl_xor_sync(0xffffffffu, mx0, 1));
        mx0 = fmaxf(mx0, __shfl_xor_sync(0xffffffffu, mx0, 2));
        mx1 = fmaxf(mx1, __shfl_xor_sync(0xffffffffu, mx1, 1));
        mx1 = fmaxf(mx1, __shfl_xor_sync(0xffffffffu, mx1, 2));

        const float mn0 = fmaxf(m0r, mx0), mn1 = fmaxf(m1r, mx1);
        const float a0 = __expf(m0r - mn0), a1 = __expf(m1r - mn1);
        float rs0 = 0.f, rs1 = 0.f;
#pragma unroll
        for (int nt = 0; nt < 8; nt++) {
            float p0 = __expf(s[nt][0] - mn0);
            float p1 = __expf(s[nt][1] - mn0);
            float p2 = __expf(s[nt][2] - mn1);
            float p3 = __expf(s[nt][3] - mn1);
            rs0 += p0 + p1;
            rs1 += p2 + p3;
            const int pa = (w * 16 + g) * (ASTR / 2) + nt * 4 + c4;
            Pu[pa]                   = h2bits(p0, p1);
            Pu[pa + 8 * (ASTR / 2)]  = h2bits(p2, p3);
        }
        rs0 += __shfl_xor_sync(0xffffffffu, rs0, 1);
        rs0 += __shfl_xor_sync(0xffffffffu, rs0, 2);
        rs1 += __shfl_xor_sync(0xffffffffu, rs1, 1);
        rs1 += __shfl_xor_sync(0xffffffffu, rs1, 2);
        l0 = l0 * a0 + rs0;
        l1 = l1 * a1 + rs1;
        m0r = mn0; m1r = mn1;
#pragma unroll
        for (int nt = 0; nt < 8; nt++) {
            o[nt][0] *= a0; o[nt][1] *= a0;
            o[nt][2] *= a1; o[nt][3] *= a1;
        }
        __syncwarp();

        // O += P V (32 fp16 MMAs; V frags via ldmatrix.x4.trans)
#pragma unroll
        for (int kc = 0; kc < 4; kc++) {
            uint32_t pf[4];
            const int pa = (w * 16 + g) * (ASTR / 2) + kc * 8 + c4;
            pf[0] = Pu[pa];
            pf[1] = Pu[pa + 8 * (ASTR / 2)];
            pf[2] = Pu[pa + 4];
            pf[3] = Pu[pa + 8 * (ASTR / 2) + 4];
#pragma unroll
            for (int ntp = 0; ntp < 4; ntp++) {
                uint32_t b0, b1, b2, b3;
                const uint32_t va = vst +
                    ((uint32_t)((kc * 16 + (lane & 15)) * ASTR) +
                     (uint32_t)((ntp * 2 + (lane >> 4)) * 8)) * 2u;
                ldsm4t(b0, b1, b2, b3, va);
                mma16(o[ntp * 2],     pf, b0, b1);
                mma16(o[ntp * 2 + 1], pf, b2, b3);
            }
        }
        __syncthreads();
    }
#undef LOAD_KV

    const float il0 = 1.f / l0, il1 = 1.f / l1;
    const int r0 = q0 + w * 16 + g;
#pragma unroll
    for (int nt = 0; nt < 8; nt++) {
        const int col = nt * 8 + 2 * c4;
        *(uint32_t*)&O[obase + (size_t)r0 * Dn + col] =
            h2bits(o[nt][0] * il0, o[nt][1] * il0);
        *(uint32_t*)&O[obase + (size_t)(r0 + 8) * Dn + col] =
            h2bits(o[nt][2] * il1, o[nt][3] * il1);
    }
}

// ---------------- launch ----------------------------------------------------
extern "C" void kernel_launch(void* const* d_in, const int* in_sizes, int n_in,
                              void* d_out, int out_size)
{
    (void)in_sizes; (void)n_in; (void)out_size;
    const float* x    = (const float*)d_in[0];
    const int*   mask = (const int*)d_in[1];
    const float* Wq   = (const float*)d_in[2];
    const float* Wk   = (const float*)d_in[3];
    const float* Wv   = (const float*)d_in[4];
    const float* Wo   = (const float*)d_in[5];
    const float* bo   = (const float*)d_in[6];
    const float* l1g  = (const float*)d_in[7];
    const float* l1b  = (const float*)d_in[8];
    const float* l2g  = (const float*)d_in[9];
    const float* l2b  = (const float*)d_in[10];
    const float* W1   = (const float*)d_in[11];
    const float* b1   = (const float*)d_in[12];
    const float* W2   = (const float*)d_in[13];
    const float* b2   = (const float*)d_in[14];
    float* out = (float*)d_out;

    __half *ph, *pqkv, *pa, *pf, *pw;
    cudaGetSymbolAddress((void**)&ph, g_h);
    cudaGetSymbolAddress((void**)&pqkv, g_qkv);
    cudaGetSymbolAddress((void**)&pa, g_att);
    cudaGetSymbolAddress((void**)&pf, g_ff);
    cudaGetSymbolAddress((void**)&pw, g_wt);

    __half* wqkvT = pw;                       // wq|wk|wv stacked, then wo
    __half* woT   = pw + 3 * 589824;
    __half* w1T   = pw + 4 * 589824;
    __half* w2T   = pw + 4 * 589824 + 2359296;

    cudaFuncSetAttribute(attn_mma_kernel,
                         cudaFuncAttributeMaxDynamicSharedMemorySize, ATT_SMEM);
    cudaFuncSetAttribute(mgemm_k<false, false, true>,
                         cudaFuncAttributeMaxDynamicSharedMemorySize, GEMM_SMEM);
    cudaFuncSetAttribute(mgemm_k<true, false, true>,
                         cudaFuncAttributeMaxDynamicSharedMemorySize, GEMM_SMEM);
    cudaFuncSetAttribute(mgemm64_k<false, true>,
                         cudaFuncAttributeMaxDynamicSharedMemorySize, GEMM64_SMEM);

    // 0) transpose weights to [N,K] K-major fp16
    dim3 tb(32, 8);
    Ptr4 p4; p4.p[0] = Wq; p4.p[1] = Wk; p4.p[2] = Wv; p4.p[3] = Wo;
    transpose4_k<<<dim3(Dn / 32, Dn / 32, 4), tb>>>(p4, wqkvT);
    transpose_k<<<dim3(DFFn / 32, Dn / 32), tb>>>(W1, w1T, Dn, DFFn);
    transpose_k<<<dim3(Dn / 32, DFFn / 32), tb>>>(W2, w2T, DFFn, Dn);

    // 1) h = ln1(x)  (fp16)
    ln_kernel<<<BTn, 192>>>(x, l1g, l1b, ph);

    // 2) qkv = h @ [Wq|Wk|Wv]  (fp16 out)
    mgemm_k<false, false, true><<<dim3(QKVs / 128, BTn / 128), 256, GEMM_SMEM>>>(
        ph, wqkvT, nullptr, nullptr, pqkv, BTn, QKVs, Dn);

    // 3) fp16 tensor-core flash attention
    attn_mma_kernel<<<dim3(Tn / 128, Hn, Bq), 256, ATT_SMEM>>>(pqkv, mask, pa);

    // 4) x2 = x + att @ Wo + bo  -> d_out (f32)
    mgemm64_k<false, true><<<dim3(Dn / 128, BTn / 64), 256, GEMM64_SMEM>>>(
        pa, woT, bo, x, out, BTn, Dn, Dn);

    // 5) h2 = ln2(x2)  (fp16)
    ln_kernel<<<BTn, 192>>>(out, l2g, l2b, ph);

    // 6) ff = relu(h2 @ W1 + b1)  (fp16 out)
    mgemm_k<true, false, true><<<dim3(DFFn / 128, BTn / 128), 256, GEMM_SMEM>>>(
        ph, w1T, b1, nullptr, pf, BTn, DFFn, Dn);

    // 7) out = x2 + ff @ W2 + b2  (f32)
    mgemm64_k<false, true><<<dim3(Dn / 128, BTn / 64), 256, GEMM64_SMEM>>>(
        pf, w2T, b2, out, out, BTn, Dn, DFFn);
}

// round 9
// speedup vs baseline: 7.5450x; 1.0337x over previous
#include <cuda_runtime.h>
#include <cuda_fp16.h>
#include <cstdint>

#define Bq 2
#define Tn 2048
#define Dn 768
#define Hn 12
#define HSn 64
#define BTn (Bq*Tn)
#define DFFn (4*Dn)
#define QKVs 2304

// ---------------- scratch (static device globals; no allocations) -----------
__device__ __half g_h[(size_t)BTn*Dn];       // ln1(x) / ln2(x2), fp16
__device__ __half g_qkv[(size_t)BTn*QKVs];   // [q|k|v] per row, fp16
__device__ __half g_att[(size_t)BTn*Dn];     // attention output, fp16
__device__ __half g_ff[(size_t)BTn*DFFn];    // relu(h2 W1 + b1), fp16
__device__ __half g_wt[4*589824 + 2*2359296];// transposed weights, fp16

// ---------------- helpers ----------------------------------------------------
__device__ __forceinline__ uint32_t smem_to_u32(const void* p) {
    uint32_t a;
    asm("{ .reg .u64 t; cvta.to.shared.u64 t, %1; cvt.u32.u64 %0, t; }"
        : "=r"(a) : "l"(p));
    return a;
}
__device__ __forceinline__ void cp16(uint32_t s, const void* g) {
    asm volatile("cp.async.cg.shared.global [%0], [%1], 16;" :: "r"(s), "l"(g));
}
#define CP_COMMIT() asm volatile("cp.async.commit_group;" ::: "memory")
#define CP_WAIT(n)  asm volatile("cp.async.wait_group %0;" :: "n"(n) : "memory")

// pack two floats -> half2 bits (lo = a, hi = b)
__device__ __forceinline__ uint32_t h2bits(float a, float b) {
    uint32_t r;
    asm("cvt.rn.f16x2.f32 %0, %1, %2;" : "=r"(r) : "f"(b), "f"(a));
    return r;
}
// fp16 mma m16n8k16, f32 accumulate
__device__ __forceinline__ void mma16(float* d, const uint32_t* a,
                                      uint32_t b0, uint32_t b1) {
    asm volatile(
        "mma.sync.aligned.m16n8k16.row.col.f32.f16.f16.f32 "
        "{%0,%1,%2,%3}, {%4,%5,%6,%7}, {%8,%9}, {%0,%1,%2,%3};"
        : "+f"(d[0]), "+f"(d[1]), "+f"(d[2]), "+f"(d[3])
        : "r"(a[0]), "r"(a[1]), "r"(a[2]), "r"(a[3]), "r"(b0), "r"(b1));
}
__device__ __forceinline__ void ldsm4(uint32_t& r0, uint32_t& r1,
                                      uint32_t& r2, uint32_t& r3, uint32_t a) {
    asm volatile(
        "ldmatrix.sync.aligned.m8n8.x4.shared.b16 {%0,%1,%2,%3}, [%4];"
        : "=r"(r0), "=r"(r1), "=r"(r2), "=r"(r3) : "r"(a));
}
__device__ __forceinline__ void ldsm4t(uint32_t& r0, uint32_t& r1,
                                       uint32_t& r2, uint32_t& r3, uint32_t a) {
    asm volatile(
        "ldmatrix.sync.aligned.m8n8.x4.trans.shared.b16 {%0,%1,%2,%3}, [%4];"
        : "=r"(r0), "=r"(r1), "=r"(r2), "=r"(r3) : "r"(a));
}

// ============== fp16 mma GEMM (128x128 tile): C = A[M,K] * BT[N,K]^T =========
// BK=64 halves, 256 threads (8 warps 2x4), warp tile 64x32, 3-stage cp.async.
#define GSTRIDE 36                         // u32 per smem row
#define GSTAGE  (128*GSTRIDE)
#define GEMM_SMEM (3*2*GSTAGE*4)           // 110592 bytes

template<bool RELU, bool RESID, bool HOUT>
__global__ void __launch_bounds__(256, 2) mgemm_k(
    const __half* __restrict__ A, const __half* __restrict__ BT,
    const float* __restrict__ bias, const float* __restrict__ R,
    void* __restrict__ Cv, int M, int N, int K)
{
    extern __shared__ __align__(16) uint32_t smu[];
    const uint32_t sb = smem_to_u32(smu);

    const int tid = threadIdx.x;
    const int wid = tid >> 5, lane = tid & 31;
    const int g = lane >> 2, c4 = lane & 3;
    const int wm = wid & 1, wn = wid >> 1;
    const int m0 = blockIdx.y * 128, n0 = blockIdx.x * 128;

    float acc[4][4][4];
#pragma unroll
    for (int i = 0; i < 4; i++)
#pragma unroll
        for (int j = 0; j < 4; j++)
#pragma unroll
            for (int e = 0; e < 4; e++) acc[i][j][e] = 0.f;

    const int NC = K >> 6;

#define LOAD_STAGE(c_, s_) do { \
    const uint32_t _da = sb + (uint32_t)((s_) * 2 * GSTAGE) * 4u; \
    const uint32_t _db = _da + GSTAGE * 4u; \
    const int _ko = (c_) * 64; \
    _Pragma("unroll") \
    for (int _e = 0; _e < 4; _e++) { \
        const int _idx = tid + _e * 256; \
        const int _r = _idx >> 3, _cg = (_idx & 7) * 8; \
        const uint32_t _so = (uint32_t)(_r * 72 + _cg) * 2u; \
        cp16(_da + _so, A  + (size_t)(m0 + _r) * K + _ko + _cg); \
        cp16(_db + _so, BT + (size_t)(n0 + _r) * K + _ko + _cg); \
    } } while (0)

    LOAD_STAGE(0, 0); CP_COMMIT();
    if (NC > 1) { LOAD_STAGE(1, 1); CP_COMMIT(); }

    for (int c = 0; c < NC; c++) {
        if (c + 1 < NC) { CP_WAIT(1); } else { CP_WAIT(0); }
        __syncthreads();
        if (c + 2 < NC) { LOAD_STAGE(c + 2, (c + 2) % 3); CP_COMMIT(); }

        const uint32_t* Asp = smu + (c % 3) * 2 * GSTAGE;
        const uint32_t* Bsp = Asp + GSTAGE;

#pragma unroll
        for (int s = 0; s < 4; s++) {
            const int kk = s * 8 + c4;
            uint32_t af[4][4], bf[4][2];
#pragma unroll
            for (int i = 0; i < 4; i++) {
                const int mm = (wm * 64 + i * 16 + g) * GSTRIDE;
                af[i][0] = Asp[mm + kk];
                af[i][1] = Asp[mm + 8 * GSTRIDE + kk];
                af[i][2] = Asp[mm + kk + 4];
                af[i][3] = Asp[mm + 8 * GSTRIDE + kk + 4];
            }
#pragma unroll
            for (int j = 0; j < 4; j++) {
                const int nn = (wn * 32 + j * 8 + g) * GSTRIDE;
                bf[j][0] = Bsp[nn + kk];
                bf[j][1] = Bsp[nn + kk + 4];
            }
#pragma unroll
            for (int i = 0; i < 4; i++)
#pragma unroll
                for (int j = 0; j < 4; j++)
                    mma16(acc[i][j], af[i], bf[j][0], bf[j][1]);
        }
    }
#undef LOAD_STAGE

#pragma unroll
    for (int i = 0; i < 4; i++) {
        const int r0 = m0 + wm * 64 + i * 16 + g;
        const int r1 = r0 + 8;
#pragma unroll
        for (int j = 0; j < 4; j++) {
            const int col = n0 + wn * 32 + j * 8 + c4 * 2;
            float v0 = acc[i][j][0], v1 = acc[i][j][1];
            float v2 = acc[i][j][2], v3 = acc[i][j][3];
            if (bias) {
                const float b0 = bias[col], b1 = bias[col + 1];
                v0 += b0; v1 += b1; v2 += b0; v3 += b1;
            }
            if (RELU) {
                v0 = fmaxf(v0, 0.f); v1 = fmaxf(v1, 0.f);
                v2 = fmaxf(v2, 0.f); v3 = fmaxf(v3, 0.f);
            }
            if (RESID) {
                const float2 ra = *(const float2*)&R[(size_t)r0 * N + col];
                const float2 rb = *(const float2*)&R[(size_t)r1 * N + col];
                v0 += ra.x; v1 += ra.y; v2 += rb.x; v3 += rb.y;
            }
            if (HOUT) {
                __half* C = (__half*)Cv;
                *(uint32_t*)&C[(size_t)r0 * N + col] = h2bits(v0, v1);
                *(uint32_t*)&C[(size_t)r1 * N + col] = h2bits(v2, v3);
            } else {
                float* C = (float*)Cv;
                *(float2*)&C[(size_t)r0 * N + col] = make_float2(v0, v1);
                *(float2*)&C[(size_t)r1 * N + col] = make_float2(v2, v3);
            }
        }
    }
}

// ============== fp16 mma GEMM (64x128 tile) — Wo / W2 (f32+resid out) =======
#define G64STAGE ((64+128)*GSTRIDE)
#define GEMM64_SMEM (3*G64STAGE*4)

template<bool RELU, bool RESID>
__global__ void __launch_bounds__(256, 2) mgemm64_k(
    const __half* __restrict__ A, const __half* __restrict__ BT,
    const float* __restrict__ bias, const float* __restrict__ R,
    float* __restrict__ C, int M, int N, int K)
{
    extern __shared__ __align__(16) uint32_t smu[];
    const uint32_t sb = smem_to_u32(smu);

    const int tid = threadIdx.x;
    const int wid = tid >> 5, lane = tid & 31;
    const int g = lane >> 2, c4 = lane & 3;
    const int wm = wid & 1, wn = wid >> 1;
    const int m0 = blockIdx.y * 64, n0 = blockIdx.x * 128;

    float acc[2][4][4];
#pragma unroll
    for (int i = 0; i < 2; i++)
#pragma unroll
        for (int j = 0; j < 4; j++)
#pragma unroll
            for (int e = 0; e < 4; e++) acc[i][j][e] = 0.f;

    const int NC = K >> 6;

#define LOAD_STAGE64(c_, s_) do { \
    const uint32_t _da = sb + (uint32_t)((s_) * G64STAGE) * 4u; \
    const uint32_t _db = _da + 64u * GSTRIDE * 4u; \
    const int _ko = (c_) * 64; \
    _Pragma("unroll") \
    for (int _e = 0; _e < 2; _e++) { \
        const int _idx = tid + _e * 256; \
        const int _r = _idx >> 3, _cg = (_idx & 7) * 8; \
        cp16(_da + (uint32_t)(_r * 72 + _cg) * 2u, \
             A + (size_t)(m0 + _r) * K + _ko + _cg); \
    } \
    _Pragma("unroll") \
    for (int _e = 0; _e < 4; _e++) { \
        const int _idx = tid + _e * 256; \
        const int _r = _idx >> 3, _cg = (_idx & 7) * 8; \
        cp16(_db + (uint32_t)(_r * 72 + _cg) * 2u, \
             BT + (size_t)(n0 + _r) * K + _ko + _cg); \
    } } while (0)

    LOAD_STAGE64(0, 0); CP_COMMIT();
    if (NC > 1) { LOAD_STAGE64(1, 1); CP_COMMIT(); }

    for (int c = 0; c < NC; c++) {
        if (c + 1 < NC) { CP_WAIT(1); } else { CP_WAIT(0); }
        __syncthreads();
        if (c + 2 < NC) { LOAD_STAGE64(c + 2, (c + 2) % 3); CP_COMMIT(); }

        const uint32_t* Asp = smu + (c % 3) * G64STAGE;
        const uint32_t* Bsp = Asp + 64 * GSTRIDE;

#pragma unroll
        for (int s = 0; s < 4; s++) {
            const int kk = s * 8 + c4;
            uint32_t af[2][4], bf[4][2];
#pragma unroll
            for (int i = 0; i < 2; i++) {
                const int mm = (wm * 32 + i * 16 + g) * GSTRIDE;
                af[i][0] = Asp[mm + kk];
                af[i][1] = Asp[mm + 8 * GSTRIDE + kk];
                af[i][2] = Asp[mm + kk + 4];
                af[i][3] = Asp[mm + 8 * GSTRIDE + kk + 4];
            }
#pragma unroll
            for (int j = 0; j < 4; j++) {
                const int nn = (wn * 32 + j * 8 + g) * GSTRIDE;
                bf[j][0] = Bsp[nn + kk];
                bf[j][1] = Bsp[nn + kk + 4];
            }
#pragma unroll
            for (int i = 0; i < 2; i++)
#pragma unroll
                for (int j = 0; j < 4; j++)
                    mma16(acc[i][j], af[i], bf[j][0], bf[j][1]);
        }
    }
#undef LOAD_STAGE64

#pragma unroll
    for (int i = 0; i < 2; i++) {
        const int r0 = m0 + wm * 32 + i * 16 + g;
        const int r1 = r0 + 8;
#pragma unroll
        for (int j = 0; j < 4; j++) {
            const int col = n0 + wn * 32 + j * 8 + c4 * 2;
            float v0 = acc[i][j][0], v1 = acc[i][j][1];
            float v2 = acc[i][j][2], v3 = acc[i][j][3];
            if (bias) {
                const float b0 = bias[col], b1 = bias[col + 1];
                v0 += b0; v1 += b1; v2 += b0; v3 += b1;
            }
            if (RELU) {
                v0 = fmaxf(v0, 0.f); v1 = fmaxf(v1, 0.f);
                v2 = fmaxf(v2, 0.f); v3 = fmaxf(v3, 0.f);
            }
            if (RESID) {
                const float2 ra = *(const float2*)&R[(size_t)r0 * N + col];
                const float2 rb = *(const float2*)&R[(size_t)r1 * N + col];
                v0 += ra.x; v1 += ra.y; v2 += rb.x; v3 += rb.y;
            }
            *(float2*)&C[(size_t)r0 * N + col] = make_float2(v0, v1);
            *(float2*)&C[(size_t)r1 * N + col] = make_float2(v2, v3);
        }
    }
}

// ---------------- batched transpose of four 768x768 weights (f32 -> f16) ----
struct Ptr4 { const float* p[4]; };
__global__ __launch_bounds__(256) void transpose4_k(Ptr4 ps, __half* __restrict__ out)
{
    __shared__ float t[32][33];
    const float* in = ps.p[blockIdx.z];
    __half* o = out + (size_t)blockIdx.z * 589824;
    const int n0 = blockIdx.x * 32, k0 = blockIdx.y * 32;
    const int x = threadIdx.x, y = threadIdx.y;
#pragma unroll
    for (int dy = 0; dy < 32; dy += 8)
        t[y + dy][x] = in[(size_t)(k0 + y + dy) * Dn + n0 + x];
    __syncthreads();
#pragma unroll
    for (int dy = 0; dy < 32; dy += 8)
        o[(size_t)(n0 + y + dy) * Dn + k0 + x] = __float2half_rn(t[x][y + dy]);
}

__global__ __launch_bounds__(256) void transpose_k(
    const float* __restrict__ in, __half* __restrict__ out, int Kd, int Nd)
{
    __shared__ float t[32][33];
    const int n0 = blockIdx.x * 32, k0 = blockIdx.y * 32;
    const int x = threadIdx.x, y = threadIdx.y;
#pragma unroll
    for (int dy = 0; dy < 32; dy += 8)
        t[y + dy][x] = in[(size_t)(k0 + y + dy) * Nd + n0 + x];
    __syncthreads();
#pragma unroll
    for (int dy = 0; dy < 32; dy += 8)
        out[(size_t)(n0 + y + dy) * Kd + k0 + x] = __float2half_rn(t[x][y + dy]);
}

// ---------------- LayerNorm: f32 in, f16 out, 192 threads/row ----------------
__global__ __launch_bounds__(192) void ln_kernel(
    const float* __restrict__ X, const float* __restrict__ g,
    const float* __restrict__ b, __half* __restrict__ Y)
{
    const int row = blockIdx.x;
    const int tid = threadIdx.x;
    const float4 v = *(const float4*)&X[(size_t)row * Dn + tid * 4];
    float s  = v.x + v.y + v.z + v.w;
    float s2 = v.x * v.x + v.y * v.y + v.z * v.z + v.w * v.w;
#pragma unroll
    for (int o = 16; o > 0; o >>= 1) {
        s  += __shfl_down_sync(0xffffffffu, s,  o);
        s2 += __shfl_down_sync(0xffffffffu, s2, o);
    }
    __shared__ float rs[6], rs2[6];
    __shared__ float sh_mean, sh_inv;
    const int w = tid >> 5, ln = tid & 31;
    if (ln == 0) { rs[w] = s; rs2[w] = s2; }
    __syncthreads();
    if (tid == 0) {
        float a = 0.f, a2 = 0.f;
#pragma unroll
        for (int i = 0; i < 6; i++) { a += rs[i]; a2 += rs2[i]; }
        float m = a * (1.f / Dn);
        float var = a2 * (1.f / Dn) - m * m;
        sh_mean = m;
        sh_inv = rsqrtf(var + 1e-5f);
    }
    __syncthreads();
    const float m = sh_mean, inv = sh_inv;
    const float4 gg = *(const float4*)&g[tid * 4];
    const float4 bb = *(const float4*)&b[tid * 4];
    uint2 u;
    u.x = h2bits((v.x - m) * inv * gg.x + bb.x, (v.y - m) * inv * gg.y + bb.y);
    u.y = h2bits((v.z - m) * inv * gg.z + bb.z, (v.w - m) * inv * gg.w + bb.w);
    *(uint2*)&Y[(size_t)row * Dn + tid * 4] = u;
}

// ============ fp16 flash attention: register-P, ldmatrix K/V, 1 sync/tile ===
// smem: Q 128x72 halves, K 2x64x72, V 2x64x72, masks 2x64 ints.
#define ASTR 72
#define ATT_SMEM (128*ASTR*2 + 4*64*ASTR*2 + 512)

__global__ void __launch_bounds__(256, 2) attn_mma_kernel(
    const __half* __restrict__ QKV, const int* __restrict__ msk,
    __half* __restrict__ O)
{
    extern __shared__ __align__(16) __half sm[];
    uint32_t* Qu = (uint32_t*)sm;                 // Q staging (dead after qf)
    const uint32_t sb   = smem_to_u32(sm);
    const uint32_t kbs0 = sb + 128 * ASTR * 2;
    const uint32_t vbs0 = kbs0 + 2 * 64 * ASTR * 2;
    const uint32_t mbs0 = vbs0 + 2 * 64 * ASTR * 2;
    int* ms0 = (int*)(sm + 128 * ASTR + 4 * 64 * ASTR);

    const int qt = blockIdx.x, h = blockIdx.y, b = blockIdx.z;
    const int tid = threadIdx.x;
    const int w = tid >> 5, lane = tid & 31;
    const int g = lane >> 2, c4 = lane & 3;
    const size_t base  = (size_t)b * Tn * QKVs + (size_t)h * HSn;
    const size_t obase = (size_t)b * Tn * Dn + (size_t)h * HSn;
    const int q0 = qt * 128;

#define LOAD_KV(kt_, st_) do { \
    const uint32_t _kb = kbs0 + (uint32_t)(st_) * 64 * ASTR * 2; \
    const uint32_t _vb = vbs0 + (uint32_t)(st_) * 64 * ASTR * 2; \
    _Pragma("unroll") \
    for (int _e = 0; _e < 2; _e++) { \
        const int _idx = tid + _e * 256; \
        const int _r = _idx >> 3, _cg = (_idx & 7) * 8; \
        const size_t _gi = base + (size_t)((kt_) + _r) * QKVs + _cg; \
        const uint32_t _so = (uint32_t)(_r * ASTR + _cg) * 2u; \
        cp16(_kb + _so, QKV + _gi + 768); \
        cp16(_vb + _so, QKV + _gi + 1536); \
    } \
    if (tid < 16) cp16(mbs0 + (uint32_t)(st_) * 256 + tid * 16, \
                       msk + b * Tn + (kt_) + tid * 4); \
    } while (0)

    // stage Q + KV tile 0
#pragma unroll
    for (int e = 0; e < 4; e++) {
        const int idx = tid + e * 256;
        const int r = idx >> 3, cg = (idx & 7) * 8;
        cp16(sb + (uint32_t)(r * ASTR + cg) * 2u,
             QKV + base + (size_t)(q0 + r) * QKVs + cg);
    }
    LOAD_KV(0, 0);
    CP_COMMIT();
    CP_WAIT(0);
    __syncthreads();

    // Q fragments -> registers (4 k16 steps)
    uint32_t qf[4][4];
#pragma unroll
    for (int kc = 0; kc < 4; kc++) {
        const int i0 = (w * 16 + g) * (ASTR / 2) + kc * 8 + c4;
        qf[kc][0] = Qu[i0];
        qf[kc][1] = Qu[i0 + 8 * (ASTR / 2)];
        qf[kc][2] = Qu[i0 + 4];
        qf[kc][3] = Qu[i0 + 8 * (ASTR / 2) + 4];
    }
    // Q buffer is dead from here on (P lives in registers) — no extra sync.

    float m0r = -1e30f, m1r = -1e30f, l0 = 0.f, l1 = 0.f;
    float o[8][4];
#pragma unroll
    for (int nt = 0; nt < 8; nt++)
#pragma unroll
        for (int e = 0; e < 4; e++) o[nt][e] = 0.f;

    const float rsc = 0.03608439182435161f;  // 768^-0.5 (embed_dim, not hs)

    // ldmatrix lane addressing (constant per thread)
    const int lrow  = ((lane >> 4) << 3) + (lane & 7);  // row within 16-block
    const int lkoff = ((lane >> 3) & 1) * 8;            // +8 k-halves for mats 1,3

    const int NT = Tn / 64;
    for (int t = 0; t < NT; t++) {
        // prefetch next KV tile into the other stage (safe: that stage was
        // fully consumed before the sync that ended iteration t-1)
        if (t + 1 < NT) { LOAD_KV((t + 1) * 64, (t + 1) & 1); CP_COMMIT(); }

        const uint32_t kst = kbs0 + (uint32_t)(t & 1) * 64 * ASTR * 2;
        const uint32_t vst = vbs0 + (uint32_t)(t & 1) * 64 * ASTR * 2;
        const int* msp = ms0 + (t & 1) * 64;

        // ---- S = Q K^T : K-frags via ldmatrix.x4 (non-trans)
        float s[8][4];
#pragma unroll
        for (int nt = 0; nt < 8; nt++)
#pragma unroll
            for (int e = 0; e < 4; e++) s[nt][e] = 0.f;
#pragma unroll
        for (int kc = 0; kc < 4; kc++) {
#pragma unroll
            for (int ntp = 0; ntp < 4; ntp++) {
                uint32_t b0, b1, b2, b3;
                const uint32_t ka = kst +
                    ((uint32_t)((ntp * 16 + lrow) * ASTR) +
                     (uint32_t)(kc * 16 + lkoff)) * 2u;
                ldsm4(b0, b1, b2, b3, ka);
                mma16(s[ntp * 2],     qf[kc], b0, b1);
                mma16(s[ntp * 2 + 1], qf[kc], b2, b3);
            }
        }

        // ---- mask + scale + online softmax (P packed straight into A-frags)
        float mx0 = -1e30f, mx1 = -1e30f;
#pragma unroll
        for (int nt = 0; nt < 8; nt++) {
            const int mk0 = msp[nt * 8 + 2 * c4], mk1 = msp[nt * 8 + 2 * c4 + 1];
            s[nt][0] = mk0 ? s[nt][0] * rsc : -1e30f;
            s[nt][1] = mk1 ? s[nt][1] * rsc : -1e30f;
            s[nt][2] = mk0 ? s[nt][2] * rsc : -1e30f;
            s[nt][3] = mk1 ? s[nt][3] * rsc : -1e30f;
            mx0 = fmaxf(mx0, fmaxf(s[nt][0], s[nt][1]));
            mx1 = fmaxf(mx1, fmaxf(s[nt][2], s[nt][3]));
        }
        mx0 = fmaxf(mx0, __shfl_xor_sync(0xffffffffu, mx0, 1));
        mx0 = fmaxf(mx0, __shfl_xor_sync(0xffffffffu, mx0, 2));
        mx1 = fmaxf(mx1, __shfl_xor_sync(0xffffffffu, mx1, 1));
        mx1 = fmaxf(mx1, __shfl_xor_sync(0xffffffffu, mx1, 2));

        const float mn0 = fmaxf(m0r, mx0), mn1 = fmaxf(m1r, mx1);
        const float a0 = __expf(m0r - mn0), a1 = __expf(m1r - mn1);
        float rs0 = 0.f, rs1 = 0.f;
        uint32_t pf[4][4];   // A-frags of P: pf[kc] = {a0,a1,a2,a3}
#pragma unroll
        for (int nt = 0; nt < 8; nt++) {
            float p0 = __expf(s[nt][0] - mn0);
            float p1 = __expf(s[nt][1] - mn0);
            float p2 = __expf(s[nt][2] - mn1);
            float p3 = __expf(s[nt][3] - mn1);
            rs0 += p0 + p1;
            rs1 += p2 + p3;
            // acc-frag of S == A-frag of PV: nt even -> slots 0,1; odd -> 2,3
            const int kc = nt >> 1;
            if ((nt & 1) == 0) {
                pf[kc][0] = h2bits(p0, p1);   // (row g,   k=2c4 pair, k0-7)
                pf[kc][1] = h2bits(p2, p3);   // (row g+8, k0-7)
            } else {
                pf[kc][2] = h2bits(p0, p1);   // (row g,   k8-15)
                pf[kc][3] = h2bits(p2, p3);   // (row g+8, k8-15)
            }
        }
        rs0 += __shfl_xor_sync(0xffffffffu, rs0, 1);
        rs0 += __shfl_xor_sync(0xffffffffu, rs0, 2);
        rs1 += __shfl_xor_sync(0xffffffffu, rs1, 1);
        rs1 += __shfl_xor_sync(0xffffffffu, rs1, 2);
        l0 = l0 * a0 + rs0;
        l1 = l1 * a1 + rs1;
        m0r = mn0; m1r = mn1;
#pragma unroll
        for (int nt = 0; nt < 8; nt++) {
            o[nt][0] *= a0; o[nt][1] *= a0;
            o[nt][2] *= a1; o[nt][3] *= a1;
        }

        // ---- O += P V (V frags via ldmatrix.x4.trans)
#pragma unroll
        for (int kc = 0; kc < 4; kc++) {
#pragma unroll
            for (int ntp = 0; ntp < 4; ntp++) {
                uint32_t b0, b1, b2, b3;
                const uint32_t va = vst +
                    ((uint32_t)((kc * 16 + (lane & 15)) * ASTR) +
                     (uint32_t)((ntp * 2 + (lane >> 4)) * 8)) * 2u;
                ldsm4t(b0, b1, b2, b3, va);
                mma16(o[ntp * 2],     pf[kc], b0, b1);
                mma16(o[ntp * 2 + 1], pf[kc], b2, b3);
            }
        }

        // one sync per tile: next-tile data ready + all warps done with this stage
        if (t + 1 < NT) {
            CP_WAIT(0);
            __syncthreads();
        }
    }
#undef LOAD_KV

    const float il0 = 1.f / l0, il1 = 1.f / l1;
    const int r0 = q0 + w * 16 + g;
#pragma unroll
    for (int nt = 0; nt < 8; nt++) {
        const int col = nt * 8 + 2 * c4;
        *(uint32_t*)&O[obase + (size_t)r0 * Dn + col] =
            h2bits(o[nt][0] * il0, o[nt][1] * il0);
        *(uint32_t*)&O[obase + (size_t)(r0 + 8) * Dn + col] =
            h2bits(o[nt][2] * il1, o[nt][3] * il1);
    }
}

// ---------------- launch ----------------------------------------------------
extern "C" void kernel_launch(void* const* d_in, const int* in_sizes, int n_in,
                              void* d_out, int out_size)
{
    (void)in_sizes; (void)n_in; (void)out_size;
    const float* x    = (const float*)d_in[0];
    const int*   mask = (const int*)d_in[1];
    const float* Wq   = (const float*)d_in[2];
    const float* Wk   = (const float*)d_in[3];
    const float* Wv   = (const float*)d_in[4];
    const float* Wo   = (const float*)d_in[5];
    const float* bo   = (const float*)d_in[6];
    const float* l1g  = (const float*)d_in[7];
    const float* l1b  = (const float*)d_in[8];
    const float* l2g  = (const float*)d_in[9];
    const float* l2b  = (const float*)d_in[10];
    const float* W1   = (const float*)d_in[11];
    const float* b1   = (const float*)d_in[12];
    const float* W2   = (const float*)d_in[13];
    const float* b2   = (const float*)d_in[14];
    float* out = (float*)d_out;

    __half *ph, *pqkv, *pa, *pf, *pw;
    cudaGetSymbolAddress((void**)&ph, g_h);
    cudaGetSymbolAddress((void**)&pqkv, g_qkv);
    cudaGetSymbolAddress((void**)&pa, g_att);
    cudaGetSymbolAddress((void**)&pf, g_ff);
    cudaGetSymbolAddress((void**)&pw, g_wt);

    __half* wqkvT = pw;                       // wq|wk|wv stacked, then wo
    __half* woT   = pw + 3 * 589824;
    __half* w1T   = pw + 4 * 589824;
    __half* w2T   = pw + 4 * 589824 + 2359296;

    cudaFuncSetAttribute(attn_mma_kernel,
                         cudaFuncAttributeMaxDynamicSharedMemorySize, ATT_SMEM);
    cudaFuncSetAttribute(mgemm_k<false, false, true>,
                         cudaFuncAttributeMaxDynamicSharedMemorySize, GEMM_SMEM);
    cudaFuncSetAttribute(mgemm_k<true, false, true>,
                         cudaFuncAttributeMaxDynamicSharedMemorySize, GEMM_SMEM);
    cudaFuncSetAttribute(mgemm64_k<false, true>,
                         cudaFuncAttributeMaxDynamicSharedMemorySize, GEMM64_SMEM);

    // 0) transpose weights to [N,K] K-major fp16
    dim3 tb(32, 8);
    Ptr4 p4; p4.p[0] = Wq; p4.p[1] = Wk; p4.p[2] = Wv; p4.p[3] = Wo;
    transpose4_k<<<dim3(Dn / 32, Dn / 32, 4), tb>>>(p4, wqkvT);
    transpose_k<<<dim3(DFFn / 32, Dn / 32), tb>>>(W1, w1T, Dn, DFFn);
    transpose_k<<<dim3(Dn / 32, DFFn / 32), tb>>>(W2, w2T, DFFn, Dn);

    // 1) h = ln1(x)  (fp16)
    ln_kernel<<<BTn, 192>>>(x, l1g, l1b, ph);

    // 2) qkv = h @ [Wq|Wk|Wv]  (fp16 out)
    mgemm_k<false, false, true><<<dim3(QKVs / 128, BTn / 128), 256, GEMM_SMEM>>>(
        ph, wqkvT, nullptr, nullptr, pqkv, BTn, QKVs, Dn);

    // 3) fp16 tensor-core flash attention
    attn_mma_kernel<<<dim3(Tn / 128, Hn, Bq), 256, ATT_SMEM>>>(pqkv, mask, pa);

    // 4) x2 = x + att @ Wo + bo  -> d_out (f32)
    mgemm64_k<false, true><<<dim3(Dn / 128, BTn / 64), 256, GEMM64_SMEM>>>(
        pa, woT, bo, x, out, BTn, Dn, Dn);

    // 5) h2 = ln2(x2)  (fp16)
    ln_kernel<<<BTn, 192>>>(out, l2g, l2b, ph);

    // 6) ff = relu(h2 @ W1 + b1)  (fp16 out)
    mgemm_k<true, false, true><<<dim3(DFFn / 128, BTn / 128), 256, GEMM_SMEM>>>(
        ph, w1T, b1, nullptr, pf, BTn, DFFn, Dn);

    // 7) out = x2 + ff @ W2 + b2  (f32)
    mgemm64_k<false, true><<<dim3(Dn / 128, BTn / 64), 256, GEMM64_SMEM>>>(
        pf, w2T, b2, out, out, BTn, Dn, DFFn);
}